// round 1
// baseline (speedup 1.0000x reference)
#include <cuda_runtime.h>
#include <math.h>

#define SEQ   4096
#define CDIM  512
#define KDIM  256
#define VDIM  512
#define NH    8
#define DK    32
#define DV    64
#define BATCH 2

// Scratch (allocation-free per harness rules)
__device__ float g_q [BATCH * SEQ * KDIM];   // scaled Q, [b][s][h*32+d]
__device__ float g_k [BATCH * SEQ * KDIM];
__device__ float g_v [BATCH * SEQ * VDIM];
__device__ float g_ao[BATCH * SEQ * VDIM];   // attention out, head-merged

// ---------------------------------------------------------------------------
// Kernel 1: fused QKV projection.
// x[b] = X[b]^T  (x[s,c] = X[b, c, s])  -> Q = x@Wq (scaled), K = x@Wk, V = x@Wv
// Tile: 64(M) x 64(N) x 16(K), 256 threads, 4x4 register blocking.
// grid: (SEQ/64, 16, BATCH); blockIdx.y: 0-3 Q cols, 4-7 K cols, 8-15 V cols.
// ---------------------------------------------------------------------------
__global__ __launch_bounds__(256) void qkv_gemm(
    const float* __restrict__ X,
    const float* __restrict__ Wq,
    const float* __restrict__ Wk,
    const float* __restrict__ Wv)
{
    __shared__ float As[16][64];
    __shared__ float Ws[16][64];

    const int b  = blockIdx.z;
    const int m0 = blockIdx.x * 64;
    const int by = blockIdx.y;

    const float* Wp; int nbase, ldw, ldo; float* outp; float scale = 1.0f;
    if (by < 4) {
        Wp = Wq; nbase = by * 64;       ldw = KDIM; ldo = KDIM;
        outp = g_q + (size_t)b * SEQ * KDIM;
        scale = 0.17677669529663687f;   // 1/sqrt(32)
    } else if (by < 8) {
        Wp = Wk; nbase = (by - 4) * 64; ldw = KDIM; ldo = KDIM;
        outp = g_k + (size_t)b * SEQ * KDIM;
    } else {
        Wp = Wv; nbase = (by - 8) * 64; ldw = VDIM; ldo = VDIM;
        outp = g_v + (size_t)b * SEQ * VDIM;
    }

    const float* A = X + (size_t)b * CDIM * SEQ;   // A[k][m] = A[k*SEQ + m]
    const int t  = threadIdx.x;
    const int tx = t & 15;
    const int ty = t >> 4;

    float acc[4][4] = {};

    for (int k0 = 0; k0 < CDIM; k0 += 16) {
        #pragma unroll
        for (int i = 0; i < 4; i++) {
            int e = t + i * 256;
            int k = e >> 6, m = e & 63;
            As[k][m] = A[(size_t)(k0 + k) * SEQ + m0 + m];
            Ws[k][m] = Wp[(size_t)(k0 + k) * ldw + nbase + m];
        }
        __syncthreads();
        #pragma unroll
        for (int kk = 0; kk < 16; kk++) {
            float4 a4 = *(const float4*)&As[kk][ty * 4];
            float4 w4 = *(const float4*)&Ws[kk][tx * 4];
            float a[4] = {a4.x, a4.y, a4.z, a4.w};
            float w[4] = {w4.x, w4.y, w4.z, w4.w};
            #pragma unroll
            for (int i = 0; i < 4; i++)
                #pragma unroll
                for (int j = 0; j < 4; j++)
                    acc[i][j] += a[i] * w[j];
        }
        __syncthreads();
    }

    #pragma unroll
    for (int i = 0; i < 4; i++) {
        int m = m0 + ty * 4 + i;
        float4 o;
        o.x = acc[i][0] * scale; o.y = acc[i][1] * scale;
        o.z = acc[i][2] * scale; o.w = acc[i][3] * scale;
        *(float4*)&outp[(size_t)m * ldo + nbase + tx * 4] = o;
    }
}

// ---------------------------------------------------------------------------
// Kernel 2: causal flash attention, per (b, head, 64-row query block).
// 256 threads: thread t -> query row r = t/4, v-col group c0 = (t%4)*16.
// Online softmax; P tile staged via SMEM for the PV product.
// ---------------------------------------------------------------------------
__global__ __launch_bounds__(256) void attn_kernel()
{
    __shared__ float Qs[64][32];
    __shared__ float Ks[64][32];
    __shared__ float Vs[64][64];
    __shared__ float Ps[64][64];

    const int qb = blockIdx.x;   // 0..63
    const int h  = blockIdx.y;
    const int b  = blockIdx.z;
    const int t  = threadIdx.x;

    const float* Qp = g_q + (size_t)b * SEQ * KDIM;
    const float* Kp = g_k + (size_t)b * SEQ * KDIM;
    const float* Vp = g_v + (size_t)b * SEQ * VDIM;

    for (int i = t; i < 64 * 32; i += 256) {
        int r = i >> 5, d = i & 31;
        Qs[r][d] = Qp[(size_t)(qb * 64 + r) * KDIM + h * DK + d];
    }
    __syncthreads();

    const int r  = t >> 2;          // query row within block
    const int c0 = (t & 3) * 16;    // v-col group start

    float qreg[32];
    #pragma unroll
    for (int d = 0; d < 32; d++) qreg[d] = Qs[r][d];

    float m_i = -1e30f, l_i = 0.0f;
    float acc[16] = {};

    for (int kb = 0; kb <= qb; kb++) {
        __syncthreads();   // prior-iter reads of Ks/Vs/Ps complete
        for (int i = t; i < 64 * 32; i += 256) {
            int rr = i >> 5, d = i & 31;
            Ks[rr][d] = Kp[(size_t)(kb * 64 + rr) * KDIM + h * DK + d];
        }
        for (int i = t; i < 64 * 64; i += 256) {
            int rr = i >> 6, d = i & 63;
            Vs[rr][d] = Vp[(size_t)(kb * 64 + rr) * VDIM + h * DV + d];
        }
        __syncthreads();

        // scores for this thread's 16 key columns
        float s[16];
        #pragma unroll
        for (int j = 0; j < 16; j++) {
            int c = c0 + j;
            const float4* krow = (const float4*)&Ks[c][0];
            float sj = 0.0f;
            #pragma unroll
            for (int d4 = 0; d4 < 8; d4++) {
                float4 kv = krow[d4];
                sj += qreg[4*d4+0] * kv.x + qreg[4*d4+1] * kv.y
                    + qreg[4*d4+2] * kv.z + qreg[4*d4+3] * kv.w;
            }
            if (kb == qb && c > r) sj = -1e30f;   // causal mask
            s[j] = sj;
        }

        // row max across 16 local + 4-thread group
        float mloc = s[0];
        #pragma unroll
        for (int j = 1; j < 16; j++) mloc = fmaxf(mloc, s[j]);
        mloc = fmaxf(mloc, __shfl_xor_sync(0xffffffff, mloc, 1));
        mloc = fmaxf(mloc, __shfl_xor_sync(0xffffffff, mloc, 2));

        float m_new = fmaxf(m_i, mloc);
        float corr  = __expf(m_i - m_new);

        float psum = 0.0f;
        #pragma unroll
        for (int j = 0; j < 16; j++) {
            float p = __expf(s[j] - m_new);
            psum += p;
            Ps[r][c0 + j] = p;
        }
        psum += __shfl_xor_sync(0xffffffff, psum, 1);
        psum += __shfl_xor_sync(0xffffffff, psum, 2);

        l_i = l_i * corr + psum;
        m_i = m_new;
        #pragma unroll
        for (int j = 0; j < 16; j++) acc[j] *= corr;

        __syncthreads();   // Ps complete

        // acc += P_row @ V
        #pragma unroll 8
        for (int kk = 0; kk < 64; kk++) {
            float p = Ps[r][kk];
            const float4* vrow = (const float4*)&Vs[kk][c0];
            #pragma unroll
            for (int q4 = 0; q4 < 4; q4++) {
                float4 vv = vrow[q4];
                acc[q4*4+0] += p * vv.x;
                acc[q4*4+1] += p * vv.y;
                acc[q4*4+2] += p * vv.z;
                acc[q4*4+3] += p * vv.w;
            }
        }
    }

    float inv = 1.0f / l_i;
    float* Op = g_ao + (size_t)b * SEQ * VDIM
              + (size_t)(qb * 64 + r) * VDIM + h * DV + c0;
    #pragma unroll
    for (int q4 = 0; q4 < 4; q4++) {
        float4 o;
        o.x = acc[q4*4+0] * inv; o.y = acc[q4*4+1] * inv;
        o.z = acc[q4*4+2] * inv; o.w = acc[q4*4+3] * inv;
        *(float4*)&Op[q4 * 4] = o;
    }
}

// ---------------------------------------------------------------------------
// Kernel 3: output projection  out = g_ao @ Wo  -> d_out [b][s][c]
// ---------------------------------------------------------------------------
__global__ __launch_bounds__(256) void out_gemm(
    const float* __restrict__ Wo, float* __restrict__ out)
{
    __shared__ float As[64][17];   // [m][k], padded
    __shared__ float Ws[16][64];

    const int b  = blockIdx.z;
    const int m0 = blockIdx.x * 64;
    const int n0 = blockIdx.y * 64;

    const float* A = g_ao + (size_t)b * SEQ * VDIM;   // row-major [m][k], ld=512
    float* C = out + (size_t)b * SEQ * CDIM;

    const int t  = threadIdx.x;
    const int tx = t & 15;
    const int ty = t >> 4;

    float acc[4][4] = {};

    for (int k0 = 0; k0 < VDIM; k0 += 16) {
        #pragma unroll
        for (int i = 0; i < 4; i++) {
            int e = t + i * 256;
            int mm = e >> 4, kk = e & 15;
            As[mm][kk] = A[(size_t)(m0 + mm) * VDIM + k0 + kk];
            int kw = e >> 6, nn = e & 63;
            Ws[kw][nn] = Wo[(size_t)(k0 + kw) * CDIM + n0 + nn];
        }
        __syncthreads();
        #pragma unroll
        for (int kk = 0; kk < 16; kk++) {
            float a[4], w[4];
            #pragma unroll
            for (int i = 0; i < 4; i++) a[i] = As[ty * 4 + i][kk];
            float4 w4 = *(const float4*)&Ws[kk][tx * 4];
            w[0] = w4.x; w[1] = w4.y; w[2] = w4.z; w[3] = w4.w;
            #pragma unroll
            for (int i = 0; i < 4; i++)
                #pragma unroll
                for (int j = 0; j < 4; j++)
                    acc[i][j] += a[i] * w[j];
        }
        __syncthreads();
    }

    #pragma unroll
    for (int i = 0; i < 4; i++) {
        int m = m0 + ty * 4 + i;
        float4 o;
        o.x = acc[i][0]; o.y = acc[i][1]; o.z = acc[i][2]; o.w = acc[i][3];
        *(float4*)&C[(size_t)m * CDIM + n0 + tx * 4] = o;
    }
}

extern "C" void kernel_launch(void* const* d_in, const int* in_sizes, int n_in,
                              void* d_out, int out_size)
{
    const float* X  = (const float*)d_in[0];
    const float* Wq = (const float*)d_in[1];
    const float* Wk = (const float*)d_in[2];
    const float* Wv = (const float*)d_in[3];
    const float* Wo = (const float*)d_in[4];
    float* out = (float*)d_out;

    dim3 g1(SEQ / 64, 16, BATCH);
    qkv_gemm<<<g1, 256>>>(X, Wq, Wk, Wv);

    dim3 g2(SEQ / 64, NH, BATCH);
    attn_kernel<<<g2, 256>>>();

    dim3 g3(SEQ / 64, CDIM / 64, BATCH);
    out_gemm<<<g3, 256>>>(Wo, out);
}

// round 2
// speedup vs baseline: 3.1912x; 3.1912x over previous
#include <cuda_runtime.h>
#include <math.h>

#define SEQ   4096
#define CDIM  512
#define KDIM  256
#define VDIM  512
#define NH    8
#define DK    32
#define DV    64
#define BATCH 2

#define BM 128
#define BN 64

// Scratch (allocation-free per harness rules)
__device__ float g_q [BATCH * SEQ * KDIM];   // scaled Q, [b][s][h*32+d]
__device__ float g_k [BATCH * SEQ * KDIM];
__device__ float g_v [BATCH * SEQ * VDIM];
__device__ float g_ao[BATCH * SEQ * VDIM];   // attention out, head-merged

// ---------------------------------------------------------------------------
// Kernel 1: fused QKV projection (unchanged from R1).
// ---------------------------------------------------------------------------
__global__ __launch_bounds__(256) void qkv_gemm(
    const float* __restrict__ X,
    const float* __restrict__ Wq,
    const float* __restrict__ Wk,
    const float* __restrict__ Wv)
{
    __shared__ float As[16][64];
    __shared__ float Ws[16][64];

    const int b  = blockIdx.z;
    const int m0 = blockIdx.x * 64;
    const int by = blockIdx.y;

    const float* Wp; int nbase, ldw, ldo; float* outp; float scale = 1.0f;
    if (by < 4) {
        Wp = Wq; nbase = by * 64;       ldw = KDIM; ldo = KDIM;
        outp = g_q + (size_t)b * SEQ * KDIM;
        scale = 0.17677669529663687f;   // 1/sqrt(32)
    } else if (by < 8) {
        Wp = Wk; nbase = (by - 4) * 64; ldw = KDIM; ldo = KDIM;
        outp = g_k + (size_t)b * SEQ * KDIM;
    } else {
        Wp = Wv; nbase = (by - 8) * 64; ldw = VDIM; ldo = VDIM;
        outp = g_v + (size_t)b * SEQ * VDIM;
    }

    const float* A = X + (size_t)b * CDIM * SEQ;   // A[k][m] = A[k*SEQ + m]
    const int t  = threadIdx.x;
    const int tx = t & 15;
    const int ty = t >> 4;

    float acc[4][4] = {};

    for (int k0 = 0; k0 < CDIM; k0 += 16) {
        #pragma unroll
        for (int i = 0; i < 4; i++) {
            int e = t + i * 256;
            int k = e >> 6, m = e & 63;
            As[k][m] = A[(size_t)(k0 + k) * SEQ + m0 + m];
            Ws[k][m] = Wp[(size_t)(k0 + k) * ldw + nbase + m];
        }
        __syncthreads();
        #pragma unroll
        for (int kk = 0; kk < 16; kk++) {
            float4 a4 = *(const float4*)&As[kk][ty * 4];
            float4 w4 = *(const float4*)&Ws[kk][tx * 4];
            float a[4] = {a4.x, a4.y, a4.z, a4.w};
            float w[4] = {w4.x, w4.y, w4.z, w4.w};
            #pragma unroll
            for (int i = 0; i < 4; i++)
                #pragma unroll
                for (int j = 0; j < 4; j++)
                    acc[i][j] += a[i] * w[j];
        }
        __syncthreads();
    }

    #pragma unroll
    for (int i = 0; i < 4; i++) {
        int m = m0 + ty * 4 + i;
        float4 o;
        o.x = acc[i][0] * scale; o.y = acc[i][1] * scale;
        o.z = acc[i][2] * scale; o.w = acc[i][3] * scale;
        *(float4*)&outp[(size_t)m * ldo + nbase + tx * 4] = o;
    }
}

// ---------------------------------------------------------------------------
// Kernel 2: causal flash attention, BM=128 q rows x BN=64 keys per tile.
// 256 threads: thread t -> 4 q-rows (ry = t>>3), 8 cols (cx = t&7).
// Q/K stored transposed in SMEM; P staged with odd pitch for conflict-free PV.
// ---------------------------------------------------------------------------
#define QT_PITCH 132   // Qt[32][132]
#define KT_PITCH 68    // Kt[32][68]
#define VS_PITCH 68    // Vs[64][68]
#define PS_PITCH 65    // Ps[128][65]
#define ATTN_SMEM ((32*QT_PITCH + 32*KT_PITCH + 64*VS_PITCH + 128*PS_PITCH) * 4)

__global__ __launch_bounds__(256, 2) void attn_kernel()
{
    extern __shared__ float sm[];
    float* Qt = sm;                          // [32][QT_PITCH]  (Qt[d][row])
    float* Kt = Qt + 32 * QT_PITCH;          // [32][KT_PITCH]  (Kt[d][col])
    float* Vs = Kt + 32 * KT_PITCH;          // [64][VS_PITCH]  (Vs[kk][vc])
    float* Ps = Vs + 64 * VS_PITCH;          // [128][PS_PITCH] (Ps[row][kk])

    const int qb = gridDim.x - 1 - blockIdx.x;   // heavy blocks first
    const int h  = blockIdx.y;
    const int b  = blockIdx.z;
    const int t  = threadIdx.x;
    const int cx = t & 7;
    const int ry = t >> 3;
    const int r0 = ry * 4;
    const int c0 = cx * 8;

    const float* Qp = g_q + ((size_t)b * SEQ + qb * BM) * KDIM + h * DK;
    const float* Kp = g_k + (size_t)b * SEQ * KDIM + h * DK;
    const float* Vp = g_v + (size_t)b * SEQ * VDIM + h * DV;

    // Load Q transposed: Qt[d][row]. Coalesced gmem read (d contiguous).
    {
        const int d = t & 31, rb = t >> 5;
        #pragma unroll
        for (int rp = 0; rp < BM; rp += 8) {
            int row = rp + rb;
            Qt[d * QT_PITCH + row] = Qp[(size_t)row * KDIM + d];
        }
    }

    float m_i[4], l_i[4], acc[4][8];
    #pragma unroll
    for (int i = 0; i < 4; i++) { m_i[i] = -1e30f; l_i[i] = 0.0f; }
    #pragma unroll
    for (int i = 0; i < 4; i++)
        #pragma unroll
        for (int j = 0; j < 8; j++) acc[i][j] = 0.0f;

    const int kb_max = 2 * qb + 1;
    for (int kb = 0; kb <= kb_max; kb++) {
        __syncthreads();   // prev PV done reading Ps/Vs (and Q fill on kb=0)

        // Fill K transposed: Kt[d][col]
        {
            const int d = t & 31, cb = t >> 5;
            #pragma unroll
            for (int cc = 0; cc < BN; cc += 8) {
                int c = cc + cb;
                Kt[d * KT_PITCH + c] = Kp[(size_t)(kb * BN + c) * KDIM + d];
            }
        }
        // Fill V row-major: Vs[kk][vc]
        for (int fi = t; fi < BN * 16; fi += 256) {
            int kk = fi >> 4, vc = (fi & 15) * 4;
            *(float4*)&Vs[kk * VS_PITCH + vc] =
                *(const float4*)&Vp[(size_t)(kb * BN + kk) * VDIM + vc];
        }
        __syncthreads();

        // ---- QK: s[4][8] = Q rows r0..r0+3 dot K cols c0..c0+7
        float s[4][8];
        #pragma unroll
        for (int i = 0; i < 4; i++)
            #pragma unroll
            for (int j = 0; j < 8; j++) s[i][j] = 0.0f;

        #pragma unroll 8
        for (int d = 0; d < 32; d++) {
            float4 q4  = *(const float4*)&Qt[d * QT_PITCH + r0];
            float4 k4a = *(const float4*)&Kt[d * KT_PITCH + c0];
            float4 k4b = *(const float4*)&Kt[d * KT_PITCH + c0 + 4];
            float qa[4] = {q4.x, q4.y, q4.z, q4.w};
            float ka[8] = {k4a.x, k4a.y, k4a.z, k4a.w,
                           k4b.x, k4b.y, k4b.z, k4b.w};
            #pragma unroll
            for (int i = 0; i < 4; i++)
                #pragma unroll
                for (int j = 0; j < 8; j++)
                    s[i][j] += qa[i] * ka[j];
        }

        // causal mask (only the last two tiles can intersect the diagonal)
        if (kb >= 2 * qb) {
            #pragma unroll
            for (int i = 0; i < 4; i++)
                #pragma unroll
                for (int j = 0; j < 8; j++)
                    if (kb * BN + c0 + j > qb * BM + r0 + i) s[i][j] = -1e30f;
        }

        // ---- online softmax (row reduce over the 8 cx lanes: xor 1,2,4)
        #pragma unroll
        for (int i = 0; i < 4; i++) {
            float mloc = s[i][0];
            #pragma unroll
            for (int j = 1; j < 8; j++) mloc = fmaxf(mloc, s[i][j]);
            mloc = fmaxf(mloc, __shfl_xor_sync(0xffffffffu, mloc, 1));
            mloc = fmaxf(mloc, __shfl_xor_sync(0xffffffffu, mloc, 2));
            mloc = fmaxf(mloc, __shfl_xor_sync(0xffffffffu, mloc, 4));

            float mn   = fmaxf(m_i[i], mloc);
            float corr = __expf(m_i[i] - mn);
            m_i[i] = mn;

            float ps = 0.0f;
            #pragma unroll
            for (int j = 0; j < 8; j++) {
                float p = __expf(s[i][j] - mn);
                ps += p;
                Ps[(r0 + i) * PS_PITCH + c0 + j] = p;
            }
            ps += __shfl_xor_sync(0xffffffffu, ps, 1);
            ps += __shfl_xor_sync(0xffffffffu, ps, 2);
            ps += __shfl_xor_sync(0xffffffffu, ps, 4);

            l_i[i] = l_i[i] * corr + ps;
            #pragma unroll
            for (int j = 0; j < 8; j++) acc[i][j] *= corr;
        }
        __syncthreads();   // Ps visible

        // ---- PV: acc[i][j] += sum_kk Ps[r0+i][kk] * Vs[kk][c0+j]
        #pragma unroll 4
        for (int kk = 0; kk < BN; kk++) {
            float p[4];
            #pragma unroll
            for (int i = 0; i < 4; i++) p[i] = Ps[(r0 + i) * PS_PITCH + kk];
            float4 va = *(const float4*)&Vs[kk * VS_PITCH + c0];
            float4 vb = *(const float4*)&Vs[kk * VS_PITCH + c0 + 4];
            float v[8] = {va.x, va.y, va.z, va.w, vb.x, vb.y, vb.z, vb.w};
            #pragma unroll
            for (int i = 0; i < 4; i++)
                #pragma unroll
                for (int j = 0; j < 8; j++)
                    acc[i][j] += p[i] * v[j];
        }
    }

    // epilogue
    float* Op = g_ao + ((size_t)b * SEQ + qb * BM + r0) * VDIM + h * DV + c0;
    #pragma unroll
    for (int i = 0; i < 4; i++) {
        float inv = 1.0f / l_i[i];
        float4 o0, o1;
        o0.x = acc[i][0] * inv; o0.y = acc[i][1] * inv;
        o0.z = acc[i][2] * inv; o0.w = acc[i][3] * inv;
        o1.x = acc[i][4] * inv; o1.y = acc[i][5] * inv;
        o1.z = acc[i][6] * inv; o1.w = acc[i][7] * inv;
        *(float4*)&Op[(size_t)i * VDIM]     = o0;
        *(float4*)&Op[(size_t)i * VDIM + 4] = o1;
    }
}

// ---------------------------------------------------------------------------
// Kernel 3: output projection  out = g_ao @ Wo  -> d_out [b][s][c]
// ---------------------------------------------------------------------------
__global__ __launch_bounds__(256) void out_gemm(
    const float* __restrict__ Wo, float* __restrict__ out)
{
    __shared__ float As[64][17];   // [m][k], padded
    __shared__ float Ws[16][64];

    const int b  = blockIdx.z;
    const int m0 = blockIdx.x * 64;
    const int n0 = blockIdx.y * 64;

    const float* A = g_ao + (size_t)b * SEQ * VDIM;   // row-major [m][k], ld=512
    float* C = out + (size_t)b * SEQ * CDIM;

    const int t  = threadIdx.x;
    const int tx = t & 15;
    const int ty = t >> 4;

    float acc[4][4] = {};

    for (int k0 = 0; k0 < VDIM; k0 += 16) {
        #pragma unroll
        for (int i = 0; i < 4; i++) {
            int e = t + i * 256;
            int mm = e >> 4, kk = e & 15;
            As[mm][kk] = A[(size_t)(m0 + mm) * VDIM + k0 + kk];
            int kw = e >> 6, nn = e & 63;
            Ws[kw][nn] = Wo[(size_t)(k0 + kw) * CDIM + n0 + nn];
        }
        __syncthreads();
        #pragma unroll
        for (int kk = 0; kk < 16; kk++) {
            float a[4], w[4];
            #pragma unroll
            for (int i = 0; i < 4; i++) a[i] = As[ty * 4 + i][kk];
            float4 w4 = *(const float4*)&Ws[kk][tx * 4];
            w[0] = w4.x; w[1] = w4.y; w[2] = w4.z; w[3] = w4.w;
            #pragma unroll
            for (int i = 0; i < 4; i++)
                #pragma unroll
                for (int j = 0; j < 4; j++)
                    acc[i][j] += a[i] * w[j];
        }
        __syncthreads();
    }

    #pragma unroll
    for (int i = 0; i < 4; i++) {
        int m = m0 + ty * 4 + i;
        float4 o;
        o.x = acc[i][0]; o.y = acc[i][1]; o.z = acc[i][2]; o.w = acc[i][3];
        *(float4*)&C[(size_t)m * CDIM + n0 + tx * 4] = o;
    }
}

extern "C" void kernel_launch(void* const* d_in, const int* in_sizes, int n_in,
                              void* d_out, int out_size)
{
    const float* X  = (const float*)d_in[0];
    const float* Wq = (const float*)d_in[1];
    const float* Wk = (const float*)d_in[2];
    const float* Wv = (const float*)d_in[3];
    const float* Wo = (const float*)d_in[4];
    float* out = (float*)d_out;

    dim3 g1(SEQ / 64, 16, BATCH);
    qkv_gemm<<<g1, 256>>>(X, Wq, Wk, Wv);

    cudaFuncSetAttribute(attn_kernel,
                         cudaFuncAttributeMaxDynamicSharedMemorySize, ATTN_SMEM);
    dim3 g2(SEQ / BM, NH, BATCH);
    attn_kernel<<<g2, 256, ATTN_SMEM>>>();

    dim3 g3(SEQ / 64, CDIM / 64, BATCH);
    out_gemm<<<g3, 256>>>(Wo, out);
}

// round 3
// speedup vs baseline: 5.3498x; 1.6764x over previous
#include <cuda_runtime.h>
#include <math.h>
#include <stdint.h>

#define SEQ   4096
#define CDIM  512
#define KDIM  256
#define VDIM  512
#define NH    8
#define DK    32
#define DV    64
#define BATCH 2

#define BM 128
#define BN 64

// Scratch (allocation-free per harness rules)
__device__ float g_q [BATCH * SEQ * KDIM];   // scaled Q, [b][s][h*32+d]
__device__ float g_k [BATCH * SEQ * KDIM];
__device__ float g_v [BATCH * SEQ * VDIM];
__device__ float g_ao[BATCH * SEQ * VDIM];   // attention out, head-merged

// ---------------------------------------------------------------------------
// Kernel 1: fused QKV projection (unchanged).
// ---------------------------------------------------------------------------
__global__ __launch_bounds__(256) void qkv_gemm(
    const float* __restrict__ X,
    const float* __restrict__ Wq,
    const float* __restrict__ Wk,
    const float* __restrict__ Wv)
{
    __shared__ float As[16][64];
    __shared__ float Ws[16][64];

    const int b  = blockIdx.z;
    const int m0 = blockIdx.x * 64;
    const int by = blockIdx.y;

    const float* Wp; int nbase, ldw, ldo; float* outp; float scale = 1.0f;
    if (by < 4) {
        Wp = Wq; nbase = by * 64;       ldw = KDIM; ldo = KDIM;
        outp = g_q + (size_t)b * SEQ * KDIM;
        scale = 0.17677669529663687f;   // 1/sqrt(32)
    } else if (by < 8) {
        Wp = Wk; nbase = (by - 4) * 64; ldw = KDIM; ldo = KDIM;
        outp = g_k + (size_t)b * SEQ * KDIM;
    } else {
        Wp = Wv; nbase = (by - 8) * 64; ldw = VDIM; ldo = VDIM;
        outp = g_v + (size_t)b * SEQ * VDIM;
    }

    const float* A = X + (size_t)b * CDIM * SEQ;
    const int t  = threadIdx.x;
    const int tx = t & 15;
    const int ty = t >> 4;

    float acc[4][4] = {};

    for (int k0 = 0; k0 < CDIM; k0 += 16) {
        #pragma unroll
        for (int i = 0; i < 4; i++) {
            int e = t + i * 256;
            int k = e >> 6, m = e & 63;
            As[k][m] = A[(size_t)(k0 + k) * SEQ + m0 + m];
            Ws[k][m] = Wp[(size_t)(k0 + k) * ldw + nbase + m];
        }
        __syncthreads();
        #pragma unroll
        for (int kk = 0; kk < 16; kk++) {
            float4 a4 = *(const float4*)&As[kk][ty * 4];
            float4 w4 = *(const float4*)&Ws[kk][tx * 4];
            float a[4] = {a4.x, a4.y, a4.z, a4.w};
            float w[4] = {w4.x, w4.y, w4.z, w4.w};
            #pragma unroll
            for (int i = 0; i < 4; i++)
                #pragma unroll
                for (int j = 0; j < 4; j++)
                    acc[i][j] += a[i] * w[j];
        }
        __syncthreads();
    }

    #pragma unroll
    for (int i = 0; i < 4; i++) {
        int m = m0 + ty * 4 + i;
        float4 o;
        o.x = acc[i][0] * scale; o.y = acc[i][1] * scale;
        o.z = acc[i][2] * scale; o.w = acc[i][3] * scale;
        *(float4*)&outp[(size_t)m * ldo + nbase + tx * 4] = o;
    }
}

// ---------------------------------------------------------------------------
// TF32 helpers
// ---------------------------------------------------------------------------
__device__ __forceinline__ unsigned tfhi(float f) {
    unsigned r;
    asm("cvt.rna.tf32.f32 %0, %1;" : "=r"(r) : "f"(f));
    return r;
}

__device__ __forceinline__ void mma8(float c[4],
                                     unsigned a0, unsigned a1, unsigned a2, unsigned a3,
                                     unsigned b0, unsigned b1)
{
    asm volatile(
        "mma.sync.aligned.m16n8k8.row.col.f32.tf32.tf32.f32 "
        "{%0,%1,%2,%3},{%4,%5,%6,%7},{%8,%9},{%0,%1,%2,%3};"
        : "+f"(c[0]), "+f"(c[1]), "+f"(c[2]), "+f"(c[3])
        : "r"(a0), "r"(a1), "r"(a2), "r"(a3), "r"(b0), "r"(b1));
}

// ---------------------------------------------------------------------------
// Kernel 2: causal flash attention with mma.sync tf32.
// 8 warps; warp w owns q-rows [16w,16w+16). BN=64 keys per tile.
// QK: 3xTF32 split (near-fp32). PV: P tf32 x (V_hi + V_lo).
// ---------------------------------------------------------------------------
#define QS_PITCH 36
#define KS_PITCH 36
#define VS_PITCH 72
#define PS_PITCH 68

#define SM_QS 0
#define SM_KS (SM_QS + 128 * QS_PITCH)          // 4608
#define SM_VH (SM_KS + 64 * KS_PITCH)           // 6912
#define SM_VL (SM_VH + 64 * VS_PITCH)           // 11520
#define SM_PS (SM_VL + 64 * VS_PITCH)           // 16128
#define ATTN_SMEM ((SM_PS + 128 * PS_PITCH) * 4)  // 99328 bytes

__global__ __launch_bounds__(256, 2) void attn_kernel()
{
    extern __shared__ float sm[];
    float* Qs = sm + SM_QS;    // [128][36] fp32
    float* Ks = sm + SM_KS;    // [64][36]  fp32
    float* Vh = sm + SM_VH;    // [64][72]  tf32 (as float bits)
    float* Vl = sm + SM_VL;    // [64][72]
    float* Ps = sm + SM_PS;    // [128][68] fp32 (per-warp private rows)

    const int qb = gridDim.x - 1 - blockIdx.x;   // heavy blocks first
    const int h  = blockIdx.y;
    const int b  = blockIdx.z;
    const int t  = threadIdx.x;
    const int w    = t >> 5;        // warp id 0..7
    const int lane = t & 31;
    const int g    = lane >> 2;     // group id 0..7
    const int tg   = lane & 3;      // thread-in-group 0..3

    const int rA = 16 * w + g;      // this thread's first q-row (in block)
    const int rB = rA + 8;

    const float* Qp = g_q + ((size_t)b * SEQ + qb * BM) * KDIM + h * DK;
    const float* Kp = g_k + (size_t)b * SEQ * KDIM + h * DK;
    const float* Vp = g_v + (size_t)b * SEQ * VDIM + h * DV;

    // Q fill (fp32)
    for (int i = t; i < BM * 32; i += 256) {
        int row = i >> 5, d = i & 31;
        Qs[row * QS_PITCH + d] = Qp[(size_t)row * KDIM + d];
    }

    float m_i[2] = {-1e30f, -1e30f};
    float l_i[2] = {0.0f, 0.0f};
    float acc[8][4];
    #pragma unroll
    for (int n = 0; n < 8; n++)
        #pragma unroll
        for (int j = 0; j < 4; j++) acc[n][j] = 0.0f;

    const int kb_max = 2 * qb + 1;
    for (int kb = 0; kb <= kb_max; kb++) {
        __syncthreads();   // prior PV reads of Vh/Vl (and Q fill on kb=0) done

        // K fill (fp32)
        for (int i = t; i < BN * 32; i += 256) {
            int key = i >> 5, d = i & 31;
            Ks[key * KS_PITCH + d] = Kp[(size_t)(kb * BN + key) * KDIM + d];
        }
        // V fill, split hi/lo tf32
        for (int i = t; i < BN * 64; i += 256) {
            int key = i >> 6, vc = i & 63;
            float v  = Vp[(size_t)(kb * BN + key) * VDIM + vc];
            unsigned hv = tfhi(v);
            float hf = __uint_as_float(hv);
            Vh[key * VS_PITCH + vc] = hf;
            Vl[key * VS_PITCH + vc] = __uint_as_float(tfhi(v - hf));
        }
        __syncthreads();

        // ---- QK: s = Q @ K^T with 3xTF32
        float s[8][4];
        #pragma unroll
        for (int n = 0; n < 8; n++)
            #pragma unroll
            for (int j = 0; j < 4; j++) s[n][j] = 0.0f;

        #pragma unroll
        for (int k8 = 0; k8 < 4; k8++) {
            const int kc = k8 * 8;
            float qa0 = Qs[rA * QS_PITCH + kc + tg];
            float qa1 = Qs[rB * QS_PITCH + kc + tg];
            float qa2 = Qs[rA * QS_PITCH + kc + tg + 4];
            float qa3 = Qs[rB * QS_PITCH + kc + tg + 4];
            unsigned ah0 = tfhi(qa0), ah1 = tfhi(qa1), ah2 = tfhi(qa2), ah3 = tfhi(qa3);
            unsigned al0 = tfhi(qa0 - __uint_as_float(ah0));
            unsigned al1 = tfhi(qa1 - __uint_as_float(ah1));
            unsigned al2 = tfhi(qa2 - __uint_as_float(ah2));
            unsigned al3 = tfhi(qa3 - __uint_as_float(ah3));

            #pragma unroll
            for (int n = 0; n < 8; n++) {
                float kb0 = Ks[(n * 8 + g) * KS_PITCH + kc + tg];
                float kb1 = Ks[(n * 8 + g) * KS_PITCH + kc + tg + 4];
                unsigned bh0 = tfhi(kb0), bh1 = tfhi(kb1);
                unsigned bl0 = tfhi(kb0 - __uint_as_float(bh0));
                unsigned bl1 = tfhi(kb1 - __uint_as_float(bh1));

                mma8(s[n], ah0, ah1, ah2, ah3, bh0, bh1);   // hi*hi
                mma8(s[n], ah0, ah1, ah2, ah3, bl0, bl1);   // hi*lo
                mma8(s[n], al0, al1, al2, al3, bh0, bh1);   // lo*hi
            }
        }

        // ---- causal mask (only tiles crossing the diagonal)
        if (kb >= 2 * qb) {
            const int rowA = qb * BM + rA;
            const int rowB = rowA + 8;
            #pragma unroll
            for (int n = 0; n < 8; n++) {
                int c = kb * BN + n * 8 + 2 * tg;
                if (c     > rowA) s[n][0] = -1e30f;
                if (c + 1 > rowA) s[n][1] = -1e30f;
                if (c     > rowB) s[n][2] = -1e30f;
                if (c + 1 > rowB) s[n][3] = -1e30f;
            }
        }

        // ---- online softmax per row (rows rA, rB)
        #pragma unroll
        for (int half = 0; half < 2; half++) {
            const int j0 = half * 2;
            float mloc = s[0][j0];
            #pragma unroll
            for (int n = 0; n < 8; n++) {
                mloc = fmaxf(mloc, s[n][j0]);
                mloc = fmaxf(mloc, s[n][j0 + 1]);
            }
            mloc = fmaxf(mloc, __shfl_xor_sync(0xffffffffu, mloc, 1));
            mloc = fmaxf(mloc, __shfl_xor_sync(0xffffffffu, mloc, 2));

            float mn   = fmaxf(m_i[half], mloc);
            float corr = __expf(m_i[half] - mn);
            m_i[half] = mn;

            const int prow = (half == 0 ? rA : rB);
            float ps = 0.0f;
            #pragma unroll
            for (int n = 0; n < 8; n++) {
                float p0 = __expf(s[n][j0]     - mn);
                float p1 = __expf(s[n][j0 + 1] - mn);
                ps += p0 + p1;
                float2 pp; pp.x = p0; pp.y = p1;
                *(float2*)&Ps[prow * PS_PITCH + n * 8 + 2 * tg] = pp;
            }
            ps += __shfl_xor_sync(0xffffffffu, ps, 1);
            ps += __shfl_xor_sync(0xffffffffu, ps, 2);

            l_i[half] = l_i[half] * corr + ps;
            #pragma unroll
            for (int n = 0; n < 8; n++) {
                acc[n][j0]     *= corr;
                acc[n][j0 + 1] *= corr;
            }
        }
        __syncwarp();   // Ps rows (warp-private) visible to all lanes

        // ---- PV: acc += P @ (V_hi + V_lo)
        #pragma unroll
        for (int k8 = 0; k8 < 8; k8++) {
            const int kc = k8 * 8;
            unsigned pa0 = tfhi(Ps[rA * PS_PITCH + kc + tg]);
            unsigned pa1 = tfhi(Ps[rB * PS_PITCH + kc + tg]);
            unsigned pa2 = tfhi(Ps[rA * PS_PITCH + kc + tg + 4]);
            unsigned pa3 = tfhi(Ps[rB * PS_PITCH + kc + tg + 4]);

            #pragma unroll
            for (int n = 0; n < 8; n++) {
                unsigned vh0 = __float_as_uint(Vh[(kc + tg)     * VS_PITCH + n * 8 + g]);
                unsigned vh1 = __float_as_uint(Vh[(kc + tg + 4) * VS_PITCH + n * 8 + g]);
                unsigned vl0 = __float_as_uint(Vl[(kc + tg)     * VS_PITCH + n * 8 + g]);
                unsigned vl1 = __float_as_uint(Vl[(kc + tg + 4) * VS_PITCH + n * 8 + g]);
                mma8(acc[n], pa0, pa1, pa2, pa3, vh0, vh1);
                mma8(acc[n], pa0, pa1, pa2, pa3, vl0, vl1);
            }
        }
    }

    // ---- epilogue
    float inv0 = 1.0f / l_i[0];
    float inv1 = 1.0f / l_i[1];
    float* Op = g_ao + ((size_t)b * SEQ + qb * BM) * VDIM + h * DV;
    #pragma unroll
    for (int n = 0; n < 8; n++) {
        float2 o0; o0.x = acc[n][0] * inv0; o0.y = acc[n][1] * inv0;
        float2 o1; o1.x = acc[n][2] * inv1; o1.y = acc[n][3] * inv1;
        *(float2*)&Op[(size_t)rA * VDIM + n * 8 + 2 * tg] = o0;
        *(float2*)&Op[(size_t)rB * VDIM + n * 8 + 2 * tg] = o1;
    }
}

// ---------------------------------------------------------------------------
// Kernel 3: output projection  out = g_ao @ Wo  -> d_out [b][s][c]
// ---------------------------------------------------------------------------
__global__ __launch_bounds__(256) void out_gemm(
    const float* __restrict__ Wo, float* __restrict__ out)
{
    __shared__ float As[64][17];
    __shared__ float Ws[16][64];

    const int b  = blockIdx.z;
    const int m0 = blockIdx.x * 64;
    const int n0 = blockIdx.y * 64;

    const float* A = g_ao + (size_t)b * SEQ * VDIM;
    float* C = out + (size_t)b * SEQ * CDIM;

    const int t  = threadIdx.x;
    const int tx = t & 15;
    const int ty = t >> 4;

    float acc[4][4] = {};

    for (int k0 = 0; k0 < VDIM; k0 += 16) {
        #pragma unroll
        for (int i = 0; i < 4; i++) {
            int e = t + i * 256;
            int mm = e >> 4, kk = e & 15;
            As[mm][kk] = A[(size_t)(m0 + mm) * VDIM + k0 + kk];
            int kw = e >> 6, nn = e & 63;
            Ws[kw][nn] = Wo[(size_t)(k0 + kw) * CDIM + n0 + nn];
        }
        __syncthreads();
        #pragma unroll
        for (int kk = 0; kk < 16; kk++) {
            float a[4], wv[4];
            #pragma unroll
            for (int i = 0; i < 4; i++) a[i] = As[ty * 4 + i][kk];
            float4 w4 = *(const float4*)&Ws[kk][tx * 4];
            wv[0] = w4.x; wv[1] = w4.y; wv[2] = w4.z; wv[3] = w4.w;
            #pragma unroll
            for (int i = 0; i < 4; i++)
                #pragma unroll
                for (int j = 0; j < 4; j++)
                    acc[i][j] += a[i] * wv[j];
        }
        __syncthreads();
    }

    #pragma unroll
    for (int i = 0; i < 4; i++) {
        int m = m0 + ty * 4 + i;
        float4 o;
        o.x = acc[i][0]; o.y = acc[i][1]; o.z = acc[i][2]; o.w = acc[i][3];
        *(float4*)&C[(size_t)m * CDIM + n0 + tx * 4] = o;
    }
}

extern "C" void kernel_launch(void* const* d_in, const int* in_sizes, int n_in,
                              void* d_out, int out_size)
{
    const float* X  = (const float*)d_in[0];
    const float* Wq = (const float*)d_in[1];
    const float* Wk = (const float*)d_in[2];
    const float* Wv = (const float*)d_in[3];
    const float* Wo = (const float*)d_in[4];
    float* out = (float*)d_out;

    dim3 g1(SEQ / 64, 16, BATCH);
    qkv_gemm<<<g1, 256>>>(X, Wq, Wk, Wv);

    cudaFuncSetAttribute(attn_kernel,
                         cudaFuncAttributeMaxDynamicSharedMemorySize, ATTN_SMEM);
    dim3 g2(SEQ / BM, NH, BATCH);
    attn_kernel<<<g2, 256, ATTN_SMEM>>>();

    dim3 g3(SEQ / 64, CDIM / 64, BATCH);
    out_gemm<<<g3, 256>>>(Wo, out);
}

// round 4
// speedup vs baseline: 6.0180x; 1.1249x over previous
#include <cuda_runtime.h>
#include <math.h>
#include <stdint.h>

#define SEQ   4096
#define CDIM  512
#define KDIM  256
#define VDIM  512
#define NH    8
#define DK    32
#define DV    64
#define BATCH 2

#define BM 128
#define BN 64

// Scratch (allocation-free per harness rules)
__device__ float g_q [BATCH * SEQ * KDIM];   // scaled Q, [b][s][h*32+d]
__device__ float g_k [BATCH * SEQ * KDIM];
__device__ float g_v [BATCH * SEQ * VDIM];
__device__ float g_ao[BATCH * SEQ * VDIM];   // attention out, head-merged

// ---------------------------------------------------------------------------
// TF32 helpers
// ---------------------------------------------------------------------------
__device__ __forceinline__ unsigned tfhi(float f) {
    unsigned r;
    asm("cvt.rna.tf32.f32 %0, %1;" : "=r"(r) : "f"(f));
    return r;
}

__device__ __forceinline__ void mma8(float c[4],
                                     unsigned a0, unsigned a1, unsigned a2, unsigned a3,
                                     unsigned b0, unsigned b1)
{
    asm volatile(
        "mma.sync.aligned.m16n8k8.row.col.f32.tf32.tf32.f32 "
        "{%0,%1,%2,%3},{%4,%5,%6,%7},{%8,%9},{%0,%1,%2,%3};"
        : "+f"(c[0]), "+f"(c[1]), "+f"(c[2]), "+f"(c[3])
        : "r"(a0), "r"(a1), "r"(a2), "r"(a3), "r"(b0), "r"(b1));
}

// ---------------------------------------------------------------------------
// Kernel 1: fused QKV projection, tf32 mma with 3x split.
// CTA: 128(M) x 64(N), K-step 32. 8 warps, each 16 rows x 64 cols.
// A = X[b]^T (X is [C][S], so A[m][k] = X[k*SEQ+m], contiguous in m).
// SMEM: Ah/Al [32][136] (k-major), Wh/Wl [32][72] (k-major).
// ---------------------------------------------------------------------------
#define GAP 136
#define GWP 72
#define QKV_SMEM ((2*32*GAP + 2*32*GWP) * 4)   // 53248 B

__global__ __launch_bounds__(256) void qkv_mma(
    const float* __restrict__ X,
    const float* __restrict__ Wq,
    const float* __restrict__ Wk,
    const float* __restrict__ Wv)
{
    extern __shared__ float smg[];
    float* Ah = smg;
    float* Al = Ah + 32 * GAP;
    float* Wh = Al + 32 * GAP;
    float* Wl = Wh + 32 * GWP;

    const int b  = blockIdx.z;
    const int m0 = blockIdx.x * 128;
    const int by = blockIdx.y;

    const float* Wp; int nbase, ldw, ldo; float* outp; float scale = 1.0f;
    if (by < 4) {
        Wp = Wq; nbase = by * 64;       ldw = KDIM; ldo = KDIM;
        outp = g_q + (size_t)b * SEQ * KDIM;
        scale = 0.17677669529663687f;   // 1/sqrt(32)
    } else if (by < 8) {
        Wp = Wk; nbase = (by - 4) * 64; ldw = KDIM; ldo = KDIM;
        outp = g_k + (size_t)b * SEQ * KDIM;
    } else {
        Wp = Wv; nbase = (by - 8) * 64; ldw = VDIM; ldo = VDIM;
        outp = g_v + (size_t)b * SEQ * VDIM;
    }

    const float* A = X + (size_t)b * CDIM * SEQ;
    const int t    = threadIdx.x;
    const int w    = t >> 5;
    const int lane = t & 31;
    const int g    = lane >> 2;
    const int tg   = lane & 3;
    const int rA   = 16 * w + g;

    float acc[8][4];
    #pragma unroll
    for (int n = 0; n < 8; n++)
        #pragma unroll
        for (int j = 0; j < 4; j++) acc[n][j] = 0.0f;

    for (int k0 = 0; k0 < CDIM; k0 += 32) {
        __syncthreads();
        // A fill: 32 k-rows x 128 m (coalesced in m)
        #pragma unroll
        for (int i = t; i < 32 * 128; i += 256) {
            int k = i >> 7, m = i & 127;
            float v = A[(size_t)(k0 + k) * SEQ + m0 + m];
            unsigned h = tfhi(v);
            Ah[k * GAP + m] = __uint_as_float(h);
            Al[k * GAP + m] = __uint_as_float(tfhi(v - __uint_as_float(h)));
        }
        // W fill: 32 k-rows x 64 n (coalesced in n)
        #pragma unroll
        for (int i = t; i < 32 * 64; i += 256) {
            int k = i >> 6, n = i & 63;
            float v = Wp[(size_t)(k0 + k) * ldw + nbase + n];
            unsigned h = tfhi(v);
            Wh[k * GWP + n] = __uint_as_float(h);
            Wl[k * GWP + n] = __uint_as_float(tfhi(v - __uint_as_float(h)));
        }
        __syncthreads();

        #pragma unroll
        for (int k8 = 0; k8 < 4; k8++) {
            const int kc = k8 * 8;
            unsigned ah0 = __float_as_uint(Ah[(kc + tg)     * GAP + rA]);
            unsigned ah1 = __float_as_uint(Ah[(kc + tg)     * GAP + rA + 8]);
            unsigned ah2 = __float_as_uint(Ah[(kc + tg + 4) * GAP + rA]);
            unsigned ah3 = __float_as_uint(Ah[(kc + tg + 4) * GAP + rA + 8]);
            unsigned al0 = __float_as_uint(Al[(kc + tg)     * GAP + rA]);
            unsigned al1 = __float_as_uint(Al[(kc + tg)     * GAP + rA + 8]);
            unsigned al2 = __float_as_uint(Al[(kc + tg + 4) * GAP + rA]);
            unsigned al3 = __float_as_uint(Al[(kc + tg + 4) * GAP + rA + 8]);

            #pragma unroll
            for (int n = 0; n < 8; n++) {
                unsigned bh0 = __float_as_uint(Wh[(kc + tg)     * GWP + n * 8 + g]);
                unsigned bh1 = __float_as_uint(Wh[(kc + tg + 4) * GWP + n * 8 + g]);
                unsigned bl0 = __float_as_uint(Wl[(kc + tg)     * GWP + n * 8 + g]);
                unsigned bl1 = __float_as_uint(Wl[(kc + tg + 4) * GWP + n * 8 + g]);
                mma8(acc[n], ah0, ah1, ah2, ah3, bh0, bh1);
                mma8(acc[n], ah0, ah1, ah2, ah3, bl0, bl1);
                mma8(acc[n], al0, al1, al2, al3, bh0, bh1);
            }
        }
    }

    #pragma unroll
    for (int n = 0; n < 8; n++) {
        float2 o0, o1;
        o0.x = acc[n][0] * scale; o0.y = acc[n][1] * scale;
        o1.x = acc[n][2] * scale; o1.y = acc[n][3] * scale;
        *(float2*)&outp[(size_t)(m0 + rA)     * ldo + nbase + n * 8 + 2 * tg] = o0;
        *(float2*)&outp[(size_t)(m0 + rA + 8) * ldo + nbase + n * 8 + 2 * tg] = o1;
    }
}

// ---------------------------------------------------------------------------
// Kernel 2: causal flash attention with mma.sync tf32.
// Pre-split K (Kh/Kl) at fill; P stored tf32-converted.
// ---------------------------------------------------------------------------
#define QS_PITCH 36
#define KS_PITCH 36
#define VS_PITCH 72
#define PS_PITCH 68

#define SM_QS 0
#define SM_KH (SM_QS + 128 * QS_PITCH)
#define SM_KL (SM_KH + 64 * KS_PITCH)
#define SM_VH (SM_KL + 64 * KS_PITCH)
#define SM_VL (SM_VH + 64 * VS_PITCH)
#define SM_PS (SM_VL + 64 * VS_PITCH)
#define ATTN_SMEM ((SM_PS + 128 * PS_PITCH) * 4)   // 108544 B

__global__ __launch_bounds__(256, 2) void attn_kernel()
{
    extern __shared__ float sm[];
    float* Qs = sm + SM_QS;    // [128][36] fp32
    float* Kh = sm + SM_KH;    // [64][36]  tf32 bits
    float* Kl = sm + SM_KL;
    float* Vh = sm + SM_VH;    // [64][72]  tf32 bits
    float* Vl = sm + SM_VL;
    float* Ps = sm + SM_PS;    // [128][68] tf32 bits (per-warp private rows)

    const int qb = gridDim.x - 1 - blockIdx.x;   // heavy blocks first
    const int h  = blockIdx.y;
    const int b  = blockIdx.z;
    const int t  = threadIdx.x;
    const int w    = t >> 5;
    const int lane = t & 31;
    const int g    = lane >> 2;
    const int tg   = lane & 3;

    const int rA = 16 * w + g;
    const int rB = rA + 8;

    const float* Qp = g_q + ((size_t)b * SEQ + qb * BM) * KDIM + h * DK;
    const float* Kp = g_k + (size_t)b * SEQ * KDIM + h * DK;
    const float* Vp = g_v + (size_t)b * SEQ * VDIM + h * DV;

    // Q fill (fp32)
    for (int i = t; i < BM * 32; i += 256) {
        int row = i >> 5, d = i & 31;
        Qs[row * QS_PITCH + d] = Qp[(size_t)row * KDIM + d];
    }

    float m_i[2] = {-1e30f, -1e30f};
    float l_i[2] = {0.0f, 0.0f};
    float acc[8][4];
    #pragma unroll
    for (int n = 0; n < 8; n++)
        #pragma unroll
        for (int j = 0; j < 4; j++) acc[n][j] = 0.0f;

    const int kb_max = 2 * qb + 1;
    for (int kb = 0; kb <= kb_max; kb++) {
        __syncthreads();

        // K fill, split hi/lo
        for (int i = t; i < BN * 32; i += 256) {
            int key = i >> 5, d = i & 31;
            float v = Kp[(size_t)(kb * BN + key) * KDIM + d];
            unsigned hv = tfhi(v);
            Kh[key * KS_PITCH + d] = __uint_as_float(hv);
            Kl[key * KS_PITCH + d] = __uint_as_float(tfhi(v - __uint_as_float(hv)));
        }
        // V fill, split hi/lo
        for (int i = t; i < BN * 64; i += 256) {
            int key = i >> 6, vc = i & 63;
            float v  = Vp[(size_t)(kb * BN + key) * VDIM + vc];
            unsigned hv = tfhi(v);
            float hf = __uint_as_float(hv);
            Vh[key * VS_PITCH + vc] = hf;
            Vl[key * VS_PITCH + vc] = __uint_as_float(tfhi(v - hf));
        }
        __syncthreads();

        // ---- QK: s = Q @ K^T with 3xTF32
        float s[8][4];
        #pragma unroll
        for (int n = 0; n < 8; n++)
            #pragma unroll
            for (int j = 0; j < 4; j++) s[n][j] = 0.0f;

        #pragma unroll
        for (int k8 = 0; k8 < 4; k8++) {
            const int kc = k8 * 8;
            float qa0 = Qs[rA * QS_PITCH + kc + tg];
            float qa1 = Qs[rB * QS_PITCH + kc + tg];
            float qa2 = Qs[rA * QS_PITCH + kc + tg + 4];
            float qa3 = Qs[rB * QS_PITCH + kc + tg + 4];
            unsigned ah0 = tfhi(qa0), ah1 = tfhi(qa1), ah2 = tfhi(qa2), ah3 = tfhi(qa3);
            unsigned al0 = tfhi(qa0 - __uint_as_float(ah0));
            unsigned al1 = tfhi(qa1 - __uint_as_float(ah1));
            unsigned al2 = tfhi(qa2 - __uint_as_float(ah2));
            unsigned al3 = tfhi(qa3 - __uint_as_float(ah3));

            #pragma unroll
            for (int n = 0; n < 8; n++) {
                unsigned bh0 = __float_as_uint(Kh[(n * 8 + g) * KS_PITCH + kc + tg]);
                unsigned bh1 = __float_as_uint(Kh[(n * 8 + g) * KS_PITCH + kc + tg + 4]);
                unsigned bl0 = __float_as_uint(Kl[(n * 8 + g) * KS_PITCH + kc + tg]);
                unsigned bl1 = __float_as_uint(Kl[(n * 8 + g) * KS_PITCH + kc + tg + 4]);

                mma8(s[n], ah0, ah1, ah2, ah3, bh0, bh1);   // hi*hi
                mma8(s[n], ah0, ah1, ah2, ah3, bl0, bl1);   // hi*lo
                mma8(s[n], al0, al1, al2, al3, bh0, bh1);   // lo*hi
            }
        }

        // ---- causal mask
        if (kb >= 2 * qb) {
            const int rowA = qb * BM + rA;
            const int rowB = rowA + 8;
            #pragma unroll
            for (int n = 0; n < 8; n++) {
                int c = kb * BN + n * 8 + 2 * tg;
                if (c     > rowA) s[n][0] = -1e30f;
                if (c + 1 > rowA) s[n][1] = -1e30f;
                if (c     > rowB) s[n][2] = -1e30f;
                if (c + 1 > rowB) s[n][3] = -1e30f;
            }
        }

        // ---- online softmax per row (rows rA, rB); store P as tf32 bits
        #pragma unroll
        for (int half = 0; half < 2; half++) {
            const int j0 = half * 2;
            float mloc = s[0][j0];
            #pragma unroll
            for (int n = 0; n < 8; n++) {
                mloc = fmaxf(mloc, s[n][j0]);
                mloc = fmaxf(mloc, s[n][j0 + 1]);
            }
            mloc = fmaxf(mloc, __shfl_xor_sync(0xffffffffu, mloc, 1));
            mloc = fmaxf(mloc, __shfl_xor_sync(0xffffffffu, mloc, 2));

            float mn   = fmaxf(m_i[half], mloc);
            float corr = __expf(m_i[half] - mn);
            m_i[half] = mn;

            const int prow = (half == 0 ? rA : rB);
            float ps = 0.0f;
            #pragma unroll
            for (int n = 0; n < 8; n++) {
                float p0 = __expf(s[n][j0]     - mn);
                float p1 = __expf(s[n][j0 + 1] - mn);
                ps += p0 + p1;
                float2 pp;
                pp.x = __uint_as_float(tfhi(p0));
                pp.y = __uint_as_float(tfhi(p1));
                *(float2*)&Ps[prow * PS_PITCH + n * 8 + 2 * tg] = pp;
            }
            ps += __shfl_xor_sync(0xffffffffu, ps, 1);
            ps += __shfl_xor_sync(0xffffffffu, ps, 2);

            l_i[half] = l_i[half] * corr + ps;
            #pragma unroll
            for (int n = 0; n < 8; n++) {
                acc[n][j0]     *= corr;
                acc[n][j0 + 1] *= corr;
            }
        }
        __syncwarp();   // Ps rows (warp-private) visible to all lanes

        // ---- PV: acc += P @ (V_hi + V_lo)
        #pragma unroll
        for (int k8 = 0; k8 < 8; k8++) {
            const int kc = k8 * 8;
            unsigned pa0 = __float_as_uint(Ps[rA * PS_PITCH + kc + tg]);
            unsigned pa1 = __float_as_uint(Ps[rB * PS_PITCH + kc + tg]);
            unsigned pa2 = __float_as_uint(Ps[rA * PS_PITCH + kc + tg + 4]);
            unsigned pa3 = __float_as_uint(Ps[rB * PS_PITCH + kc + tg + 4]);

            #pragma unroll
            for (int n = 0; n < 8; n++) {
                unsigned vh0 = __float_as_uint(Vh[(kc + tg)     * VS_PITCH + n * 8 + g]);
                unsigned vh1 = __float_as_uint(Vh[(kc + tg + 4) * VS_PITCH + n * 8 + g]);
                unsigned vl0 = __float_as_uint(Vl[(kc + tg)     * VS_PITCH + n * 8 + g]);
                unsigned vl1 = __float_as_uint(Vl[(kc + tg + 4) * VS_PITCH + n * 8 + g]);
                mma8(acc[n], pa0, pa1, pa2, pa3, vh0, vh1);
                mma8(acc[n], pa0, pa1, pa2, pa3, vl0, vl1);
            }
        }
    }

    // ---- epilogue
    float inv0 = 1.0f / l_i[0];
    float inv1 = 1.0f / l_i[1];
    float* Op = g_ao + ((size_t)b * SEQ + qb * BM) * VDIM + h * DV;
    #pragma unroll
    for (int n = 0; n < 8; n++) {
        float2 o0; o0.x = acc[n][0] * inv0; o0.y = acc[n][1] * inv0;
        float2 o1; o1.x = acc[n][2] * inv1; o1.y = acc[n][3] * inv1;
        *(float2*)&Op[(size_t)rA * VDIM + n * 8 + 2 * tg] = o0;
        *(float2*)&Op[(size_t)rB * VDIM + n * 8 + 2 * tg] = o1;
    }
}

// ---------------------------------------------------------------------------
// Kernel 3: output projection tf32 mma, out = g_ao @ Wo.
// A row-major [m][k] (contiguous k) -> As[m][36]; W k-major -> [32][72].
// ---------------------------------------------------------------------------
#define OAP 36
#define OWP 72
#define OUT_SMEM ((2*128*OAP + 2*32*OWP) * 4)   // 55296 B

__global__ __launch_bounds__(256) void out_mma(
    const float* __restrict__ Wo, float* __restrict__ out)
{
    extern __shared__ float smo[];
    float* Ah = smo;
    float* Al = Ah + 128 * OAP;
    float* Wh = Al + 128 * OAP;
    float* Wl = Wh + 32 * OWP;

    const int b  = blockIdx.z;
    const int m0 = blockIdx.x * 128;
    const int n0 = blockIdx.y * 64;

    const float* A = g_ao + (size_t)b * SEQ * VDIM;
    float* C = out + (size_t)b * SEQ * CDIM;

    const int t    = threadIdx.x;
    const int w    = t >> 5;
    const int lane = t & 31;
    const int g    = lane >> 2;
    const int tg   = lane & 3;
    const int rA   = 16 * w + g;

    float acc[8][4];
    #pragma unroll
    for (int n = 0; n < 8; n++)
        #pragma unroll
        for (int j = 0; j < 4; j++) acc[n][j] = 0.0f;

    for (int k0 = 0; k0 < VDIM; k0 += 32) {
        __syncthreads();
        // A fill: 128 m-rows x 32 k (coalesced in k)
        #pragma unroll
        for (int i = t; i < 128 * 32; i += 256) {
            int m = i >> 5, k = i & 31;
            float v = A[(size_t)(m0 + m) * VDIM + k0 + k];
            unsigned hv = tfhi(v);
            Ah[m * OAP + k] = __uint_as_float(hv);
            Al[m * OAP + k] = __uint_as_float(tfhi(v - __uint_as_float(hv)));
        }
        // W fill: 32 k-rows x 64 n (coalesced in n)
        #pragma unroll
        for (int i = t; i < 32 * 64; i += 256) {
            int k = i >> 6, n = i & 63;
            float v = Wo[(size_t)(k0 + k) * CDIM + n0 + n];
            unsigned hv = tfhi(v);
            Wh[k * OWP + n] = __uint_as_float(hv);
            Wl[k * OWP + n] = __uint_as_float(tfhi(v - __uint_as_float(hv)));
        }
        __syncthreads();

        #pragma unroll
        for (int k8 = 0; k8 < 4; k8++) {
            const int kc = k8 * 8;
            unsigned ah0 = __float_as_uint(Ah[rA       * OAP + kc + tg]);
            unsigned ah1 = __float_as_uint(Ah[(rA + 8) * OAP + kc + tg]);
            unsigned ah2 = __float_as_uint(Ah[rA       * OAP + kc + tg + 4]);
            unsigned ah3 = __float_as_uint(Ah[(rA + 8) * OAP + kc + tg + 4]);
            unsigned al0 = __float_as_uint(Al[rA       * OAP + kc + tg]);
            unsigned al1 = __float_as_uint(Al[(rA + 8) * OAP + kc + tg]);
            unsigned al2 = __float_as_uint(Al[rA       * OAP + kc + tg + 4]);
            unsigned al3 = __float_as_uint(Al[(rA + 8) * OAP + kc + tg + 4]);

            #pragma unroll
            for (int n = 0; n < 8; n++) {
                unsigned bh0 = __float_as_uint(Wh[(kc + tg)     * OWP + n * 8 + g]);
                unsigned bh1 = __float_as_uint(Wh[(kc + tg + 4) * OWP + n * 8 + g]);
                unsigned bl0 = __float_as_uint(Wl[(kc + tg)     * OWP + n * 8 + g]);
                unsigned bl1 = __float_as_uint(Wl[(kc + tg + 4) * OWP + n * 8 + g]);
                mma8(acc[n], ah0, ah1, ah2, ah3, bh0, bh1);
                mma8(acc[n], ah0, ah1, ah2, ah3, bl0, bl1);
                mma8(acc[n], al0, al1, al2, al3, bh0, bh1);
            }
        }
    }

    #pragma unroll
    for (int n = 0; n < 8; n++) {
        float2 o0, o1;
        o0.x = acc[n][0]; o0.y = acc[n][1];
        o1.x = acc[n][2]; o1.y = acc[n][3];
        *(float2*)&C[(size_t)(m0 + rA)     * CDIM + n0 + n * 8 + 2 * tg] = o0;
        *(float2*)&C[(size_t)(m0 + rA + 8) * CDIM + n0 + n * 8 + 2 * tg] = o1;
    }
}

extern "C" void kernel_launch(void* const* d_in, const int* in_sizes, int n_in,
                              void* d_out, int out_size)
{
    const float* X  = (const float*)d_in[0];
    const float* Wq = (const float*)d_in[1];
    const float* Wk = (const float*)d_in[2];
    const float* Wv = (const float*)d_in[3];
    const float* Wo = (const float*)d_in[4];
    float* out = (float*)d_out;

    cudaFuncSetAttribute(qkv_mma,
                         cudaFuncAttributeMaxDynamicSharedMemorySize, QKV_SMEM);
    cudaFuncSetAttribute(attn_kernel,
                         cudaFuncAttributeMaxDynamicSharedMemorySize, ATTN_SMEM);
    cudaFuncSetAttribute(out_mma,
                         cudaFuncAttributeMaxDynamicSharedMemorySize, OUT_SMEM);

    dim3 g1(SEQ / 128, 16, BATCH);
    qkv_mma<<<g1, 256, QKV_SMEM>>>(X, Wq, Wk, Wv);

    dim3 g2(SEQ / BM, NH, BATCH);
    attn_kernel<<<g2, 256, ATTN_SMEM>>>();

    dim3 g3(SEQ / 128, CDIM / 64, BATCH);
    out_mma<<<g3, 256, OUT_SMEM>>>(Wo, out);
}

// round 5
// speedup vs baseline: 8.4068x; 1.3969x over previous
#include <cuda_runtime.h>
#include <math.h>
#include <stdint.h>

#define SEQ   4096
#define CDIM  512
#define KDIM  256
#define VDIM  512
#define NH    8
#define DK    32
#define DV    64
#define BATCH 2

#define BM 128
#define BN 64

// Scratch (allocation-free per harness rules)
__device__ float g_q [BATCH * SEQ * KDIM];   // scaled Q, [b][s][h*32+d]
__device__ float g_k [BATCH * SEQ * KDIM];
__device__ float g_v [BATCH * SEQ * VDIM];
__device__ float g_ao[BATCH * SEQ * VDIM];   // attention out, head-merged

// ---------------------------------------------------------------------------
// bf16 helpers: split (v0,v1) pair into hi/lo bf16x2 words (elem0 in low half)
// ---------------------------------------------------------------------------
__device__ __forceinline__ void bsplit(float v0, float v1, unsigned& hi, unsigned& lo)
{
    asm("cvt.rn.bf16x2.f32 %0, %1, %2;" : "=r"(hi) : "f"(v1), "f"(v0));
    float h0 = __uint_as_float(hi << 16);
    float h1 = __uint_as_float(hi & 0xffff0000u);
    asm("cvt.rn.bf16x2.f32 %0, %1, %2;" : "=r"(lo) : "f"(v1 - h1), "f"(v0 - h0));
}

__device__ __forceinline__ void mma16(float c[4],
                                      unsigned a0, unsigned a1, unsigned a2, unsigned a3,
                                      unsigned b0, unsigned b1)
{
    asm volatile(
        "mma.sync.aligned.m16n8k16.row.col.f32.bf16.bf16.f32 "
        "{%0,%1,%2,%3},{%4,%5,%6,%7},{%8,%9},{%0,%1,%2,%3};"
        : "+f"(c[0]), "+f"(c[1]), "+f"(c[2]), "+f"(c[3])
        : "r"(a0), "r"(a1), "r"(a2), "r"(a3), "r"(b0), "r"(b1));
}

// ---------------------------------------------------------------------------
// Kernel 1: fused QKV projection, bf16 mma, 3-term split.
// CTA: 128(M) x 64(N), K-step 32 (16 bf16x2 pairs). 8 warps.
// SMEM: Ah/Al [128 m][20 kp], Wth/Wtl [64 n][20 kp] (k-pair packed).
// ---------------------------------------------------------------------------
#define AP 20
#define WP 20
#define QKV_SMEM ((2*128*AP + 2*64*WP) * 4)   // 30720 B

__global__ __launch_bounds__(256) void qkv_mma(
    const float* __restrict__ X,
    const float* __restrict__ Wq,
    const float* __restrict__ Wk,
    const float* __restrict__ Wv)
{
    extern __shared__ unsigned smg[];
    unsigned* Ah  = smg;
    unsigned* Al  = Ah  + 128 * AP;
    unsigned* Wth = Al  + 128 * AP;
    unsigned* Wtl = Wth + 64 * WP;

    const int b  = blockIdx.z;
    const int m0 = blockIdx.x * 128;
    const int by = blockIdx.y;

    const float* Wpt; int nbase, ldw, ldo; float* outp; float scale = 1.0f;
    if (by < 4) {
        Wpt = Wq; nbase = by * 64;       ldw = KDIM; ldo = KDIM;
        outp = g_q + (size_t)b * SEQ * KDIM;
        scale = 0.17677669529663687f;   // 1/sqrt(32)
    } else if (by < 8) {
        Wpt = Wk; nbase = (by - 4) * 64; ldw = KDIM; ldo = KDIM;
        outp = g_k + (size_t)b * SEQ * KDIM;
    } else {
        Wpt = Wv; nbase = (by - 8) * 64; ldw = VDIM; ldo = VDIM;
        outp = g_v + (size_t)b * SEQ * VDIM;
    }

    const float* A = X + (size_t)b * CDIM * SEQ;   // A[k][m] = X[k*SEQ+m]
    const int t    = threadIdx.x;
    const int w    = t >> 5;
    const int lane = t & 31;
    const int g    = lane >> 2;
    const int tg   = lane & 3;
    const int rA   = 16 * w + g;
    const int rB   = rA + 8;

    float acc[8][4];
    #pragma unroll
    for (int n = 0; n < 8; n++)
        #pragma unroll
        for (int j = 0; j < 4; j++) acc[n][j] = 0.0f;

    for (int k0 = 0; k0 < CDIM; k0 += 32) {
        __syncthreads();
        // A fill: pairs along k, from two gmem rows (coalesced in m)
        #pragma unroll
        for (int i = t; i < 128 * 16; i += 256) {
            int m = i & 127, kp = i >> 7;
            float v0 = A[(size_t)(k0 + 2 * kp)     * SEQ + m0 + m];
            float v1 = A[(size_t)(k0 + 2 * kp + 1) * SEQ + m0 + m];
            unsigned hi, lo; bsplit(v0, v1, hi, lo);
            Ah[m * AP + kp] = hi; Al[m * AP + kp] = lo;
        }
        // W fill transposed: Wt[n][kp]
        #pragma unroll
        for (int i = t; i < 64 * 16; i += 256) {
            int n = i & 63, kp = i >> 6;
            float v0 = Wpt[(size_t)(k0 + 2 * kp)     * ldw + nbase + n];
            float v1 = Wpt[(size_t)(k0 + 2 * kp + 1) * ldw + nbase + n];
            unsigned hi, lo; bsplit(v0, v1, hi, lo);
            Wth[n * WP + kp] = hi; Wtl[n * WP + kp] = lo;
        }
        __syncthreads();

        #pragma unroll
        for (int kc2 = 0; kc2 < 2; kc2++) {
            const int kp0 = kc2 * 8;
            unsigned ah0 = Ah[rA * AP + kp0 + tg];
            unsigned ah1 = Ah[rB * AP + kp0 + tg];
            unsigned ah2 = Ah[rA * AP + kp0 + tg + 4];
            unsigned ah3 = Ah[rB * AP + kp0 + tg + 4];
            unsigned al0 = Al[rA * AP + kp0 + tg];
            unsigned al1 = Al[rB * AP + kp0 + tg];
            unsigned al2 = Al[rA * AP + kp0 + tg + 4];
            unsigned al3 = Al[rB * AP + kp0 + tg + 4];

            #pragma unroll
            for (int n = 0; n < 8; n++) {
                unsigned bh0 = Wth[(n * 8 + g) * WP + kp0 + tg];
                unsigned bh1 = Wth[(n * 8 + g) * WP + kp0 + tg + 4];
                unsigned bl0 = Wtl[(n * 8 + g) * WP + kp0 + tg];
                unsigned bl1 = Wtl[(n * 8 + g) * WP + kp0 + tg + 4];
                mma16(acc[n], ah0, ah1, ah2, ah3, bh0, bh1);
                mma16(acc[n], ah0, ah1, ah2, ah3, bl0, bl1);
                mma16(acc[n], al0, al1, al2, al3, bh0, bh1);
            }
        }
    }

    #pragma unroll
    for (int n = 0; n < 8; n++) {
        float2 o0, o1;
        o0.x = acc[n][0] * scale; o0.y = acc[n][1] * scale;
        o1.x = acc[n][2] * scale; o1.y = acc[n][3] * scale;
        *(float2*)&outp[(size_t)(m0 + rA) * ldo + nbase + n * 8 + 2 * tg] = o0;
        *(float2*)&outp[(size_t)(m0 + rB) * ldo + nbase + n * 8 + 2 * tg] = o1;
    }
}

// ---------------------------------------------------------------------------
// Kernel 2: causal flash attention, bf16 m16n8k16 with hi/lo splits.
// Q/K pre-split k-pair packed; V packed transposed (key-pairs); P split bf16.
// ---------------------------------------------------------------------------
#define QP 20    // Q  [128 rows][20]  (16 k-pairs + pad)
#define KP 20    // K  [64 keys][20]
#define VTP 36   // Vt [64 cols][36]   (32 key-pairs + pad)
#define PP 36    // Ps [128 rows][36]  (32 key-pairs + pad)

#define SM_QH 0
#define SM_QL (SM_QH + 128 * QP)
#define SM_KH (SM_QL + 128 * QP)
#define SM_KL (SM_KH + 64 * KP)
#define SM_VH (SM_KL + 64 * KP)
#define SM_VL (SM_VH + 64 * VTP)
#define SM_PH (SM_VL + 64 * VTP)
#define SM_PL (SM_PH + 128 * PP)
#define ATTN_SMEM ((SM_PL + 128 * PP) * 4)   // 86016 B

__global__ __launch_bounds__(256, 2) void attn_kernel()
{
    extern __shared__ unsigned sma[];
    unsigned* Qh  = sma + SM_QH;
    unsigned* Ql  = sma + SM_QL;
    unsigned* Kh  = sma + SM_KH;
    unsigned* Kl  = sma + SM_KL;
    unsigned* Vth = sma + SM_VH;
    unsigned* Vtl = sma + SM_VL;
    unsigned* Psh = sma + SM_PH;
    unsigned* Psl = sma + SM_PL;

    const int qb = gridDim.x - 1 - blockIdx.x;   // heavy blocks first
    const int h  = blockIdx.y;
    const int b  = blockIdx.z;
    const int t  = threadIdx.x;
    const int w    = t >> 5;
    const int lane = t & 31;
    const int g    = lane >> 2;
    const int tg   = lane & 3;

    const int rA = 16 * w + g;
    const int rB = rA + 8;

    const float* Qp = g_q + ((size_t)b * SEQ + qb * BM) * KDIM + h * DK;
    const float* Kp = g_k + (size_t)b * SEQ * KDIM + h * DK;
    const float* Vp = g_v + (size_t)b * SEQ * VDIM + h * DV;

    // Q fill: pairs along d
    for (int i = t; i < BM * 16; i += 256) {
        int row = i >> 4, kp = i & 15;
        float2 v2 = *(const float2*)&Qp[(size_t)row * KDIM + 2 * kp];
        unsigned hi, lo; bsplit(v2.x, v2.y, hi, lo);
        Qh[row * QP + kp] = hi; Ql[row * QP + kp] = lo;
    }

    float m_i[2] = {-1e30f, -1e30f};
    float l_i[2] = {0.0f, 0.0f};
    float acc[8][4];
    #pragma unroll
    for (int n = 0; n < 8; n++)
        #pragma unroll
        for (int j = 0; j < 4; j++) acc[n][j] = 0.0f;

    const int kb_max = 2 * qb + 1;
    for (int kb = 0; kb <= kb_max; kb++) {
        __syncthreads();

        // K fill: pairs along d
        for (int i = t; i < BN * 16; i += 256) {
            int key = i >> 4, kp = i & 15;
            float2 v2 = *(const float2*)&Kp[(size_t)(kb * BN + key) * KDIM + 2 * kp];
            unsigned hi, lo; bsplit(v2.x, v2.y, hi, lo);
            Kh[key * KP + kp] = hi; Kl[key * KP + kp] = lo;
        }
        // V fill transposed: Vt[col][key-pair]
        for (int i = t; i < 64 * 32; i += 256) {
            int vc = i & 63, pr = i >> 6;
            float v0 = Vp[(size_t)(kb * BN + 2 * pr)     * VDIM + vc];
            float v1 = Vp[(size_t)(kb * BN + 2 * pr + 1) * VDIM + vc];
            unsigned hi, lo; bsplit(v0, v1, hi, lo);
            Vth[vc * VTP + pr] = hi; Vtl[vc * VTP + pr] = lo;
        }
        __syncthreads();

        // ---- QK: s = Q @ K^T, 3-term bf16
        float s[8][4];
        #pragma unroll
        for (int n = 0; n < 8; n++)
            #pragma unroll
            for (int j = 0; j < 4; j++) s[n][j] = 0.0f;

        #pragma unroll
        for (int kc2 = 0; kc2 < 2; kc2++) {
            const int kp0 = kc2 * 8;
            unsigned ah0 = Qh[rA * QP + kp0 + tg];
            unsigned ah1 = Qh[rB * QP + kp0 + tg];
            unsigned ah2 = Qh[rA * QP + kp0 + tg + 4];
            unsigned ah3 = Qh[rB * QP + kp0 + tg + 4];
            unsigned al0 = Ql[rA * QP + kp0 + tg];
            unsigned al1 = Ql[rB * QP + kp0 + tg];
            unsigned al2 = Ql[rA * QP + kp0 + tg + 4];
            unsigned al3 = Ql[rB * QP + kp0 + tg + 4];

            #pragma unroll
            for (int n = 0; n < 8; n++) {
                unsigned bh0 = Kh[(n * 8 + g) * KP + kp0 + tg];
                unsigned bh1 = Kh[(n * 8 + g) * KP + kp0 + tg + 4];
                unsigned bl0 = Kl[(n * 8 + g) * KP + kp0 + tg];
                unsigned bl1 = Kl[(n * 8 + g) * KP + kp0 + tg + 4];
                mma16(s[n], ah0, ah1, ah2, ah3, bh0, bh1);   // hi*hi
                mma16(s[n], ah0, ah1, ah2, ah3, bl0, bl1);   // hi*lo
                mma16(s[n], al0, al1, al2, al3, bh0, bh1);   // lo*hi
            }
        }

        // ---- causal mask
        if (kb >= 2 * qb) {
            const int rowA = qb * BM + rA;
            const int rowB = rowA + 8;
            #pragma unroll
            for (int n = 0; n < 8; n++) {
                int c = kb * BN + n * 8 + 2 * tg;
                if (c     > rowA) s[n][0] = -1e30f;
                if (c + 1 > rowA) s[n][1] = -1e30f;
                if (c     > rowB) s[n][2] = -1e30f;
                if (c + 1 > rowB) s[n][3] = -1e30f;
            }
        }

        // ---- online softmax (rows rA, rB); store P split bf16
        #pragma unroll
        for (int half = 0; half < 2; half++) {
            const int j0 = half * 2;
            float mloc = s[0][j0];
            #pragma unroll
            for (int n = 0; n < 8; n++) {
                mloc = fmaxf(mloc, s[n][j0]);
                mloc = fmaxf(mloc, s[n][j0 + 1]);
            }
            mloc = fmaxf(mloc, __shfl_xor_sync(0xffffffffu, mloc, 1));
            mloc = fmaxf(mloc, __shfl_xor_sync(0xffffffffu, mloc, 2));

            float mn   = fmaxf(m_i[half], mloc);
            float corr = __expf(m_i[half] - mn);
            m_i[half] = mn;

            const int prow = (half == 0 ? rA : rB);
            float ps = 0.0f;
            #pragma unroll
            for (int n = 0; n < 8; n++) {
                float p0 = __expf(s[n][j0]     - mn);
                float p1 = __expf(s[n][j0 + 1] - mn);
                ps += p0 + p1;
                unsigned hi, lo; bsplit(p0, p1, hi, lo);
                Psh[prow * PP + n * 4 + tg] = hi;
                Psl[prow * PP + n * 4 + tg] = lo;
            }
            ps += __shfl_xor_sync(0xffffffffu, ps, 1);
            ps += __shfl_xor_sync(0xffffffffu, ps, 2);

            l_i[half] = l_i[half] * corr + ps;
            #pragma unroll
            for (int n = 0; n < 8; n++) {
                acc[n][j0]     *= corr;
                acc[n][j0 + 1] *= corr;
            }
        }
        __syncwarp();   // Ps rows are warp-private

        // ---- PV: acc += (P_hi + P_lo) @ V_hi + P_hi @ V_lo
        #pragma unroll
        for (int kc2 = 0; kc2 < 4; kc2++) {
            const int kp0 = kc2 * 8;
            unsigned ph0 = Psh[rA * PP + kp0 + tg];
            unsigned ph1 = Psh[rB * PP + kp0 + tg];
            unsigned ph2 = Psh[rA * PP + kp0 + tg + 4];
            unsigned ph3 = Psh[rB * PP + kp0 + tg + 4];
            unsigned pl0 = Psl[rA * PP + kp0 + tg];
            unsigned pl1 = Psl[rB * PP + kp0 + tg];
            unsigned pl2 = Psl[rA * PP + kp0 + tg + 4];
            unsigned pl3 = Psl[rB * PP + kp0 + tg + 4];

            #pragma unroll
            for (int n = 0; n < 8; n++) {
                unsigned vh0 = Vth[(n * 8 + g) * VTP + kp0 + tg];
                unsigned vh1 = Vth[(n * 8 + g) * VTP + kp0 + tg + 4];
                unsigned vl0 = Vtl[(n * 8 + g) * VTP + kp0 + tg];
                unsigned vl1 = Vtl[(n * 8 + g) * VTP + kp0 + tg + 4];
                mma16(acc[n], ph0, ph1, ph2, ph3, vh0, vh1);
                mma16(acc[n], pl0, pl1, pl2, pl3, vh0, vh1);
                mma16(acc[n], ph0, ph1, ph2, ph3, vl0, vl1);
            }
        }
    }

    // ---- epilogue
    float inv0 = 1.0f / l_i[0];
    float inv1 = 1.0f / l_i[1];
    float* Op = g_ao + ((size_t)b * SEQ + qb * BM) * VDIM + h * DV;
    #pragma unroll
    for (int n = 0; n < 8; n++) {
        float2 o0; o0.x = acc[n][0] * inv0; o0.y = acc[n][1] * inv0;
        float2 o1; o1.x = acc[n][2] * inv1; o1.y = acc[n][3] * inv1;
        *(float2*)&Op[(size_t)rA * VDIM + n * 8 + 2 * tg] = o0;
        *(float2*)&Op[(size_t)rB * VDIM + n * 8 + 2 * tg] = o1;
    }
}

// ---------------------------------------------------------------------------
// Kernel 3: output projection bf16 mma, out = g_ao @ Wo.
// ---------------------------------------------------------------------------
#define OUT_SMEM ((2*128*AP + 2*64*WP) * 4)   // 30720 B

__global__ __launch_bounds__(256) void out_mma(
    const float* __restrict__ Wo, float* __restrict__ out)
{
    extern __shared__ unsigned smo[];
    unsigned* Ah  = smo;
    unsigned* Al  = Ah  + 128 * AP;
    unsigned* Wth = Al  + 128 * AP;
    unsigned* Wtl = Wth + 64 * WP;

    const int b  = blockIdx.z;
    const int m0 = blockIdx.x * 128;
    const int n0 = blockIdx.y * 64;

    const float* A = g_ao + (size_t)b * SEQ * VDIM;   // row-major [m][k]
    float* C = out + (size_t)b * SEQ * CDIM;

    const int t    = threadIdx.x;
    const int w    = t >> 5;
    const int lane = t & 31;
    const int g    = lane >> 2;
    const int tg   = lane & 3;
    const int rA   = 16 * w + g;
    const int rB   = rA + 8;

    float acc[8][4];
    #pragma unroll
    for (int n = 0; n < 8; n++)
        #pragma unroll
        for (int j = 0; j < 4; j++) acc[n][j] = 0.0f;

    for (int k0 = 0; k0 < VDIM; k0 += 32) {
        __syncthreads();
        // A fill: float2 along k (coalesced)
        #pragma unroll
        for (int i = t; i < 128 * 16; i += 256) {
            int m = i >> 4, kp = i & 15;
            float2 v2 = *(const float2*)&A[(size_t)(m0 + m) * VDIM + k0 + 2 * kp];
            unsigned hi, lo; bsplit(v2.x, v2.y, hi, lo);
            Ah[m * AP + kp] = hi; Al[m * AP + kp] = lo;
        }
        // W fill transposed
        #pragma unroll
        for (int i = t; i < 64 * 16; i += 256) {
            int n = i & 63, kp = i >> 6;
            float v0 = Wo[(size_t)(k0 + 2 * kp)     * CDIM + n0 + n];
            float v1 = Wo[(size_t)(k0 + 2 * kp + 1) * CDIM + n0 + n];
            unsigned hi, lo; bsplit(v0, v1, hi, lo);
            Wth[n * WP + kp] = hi; Wtl[n * WP + kp] = lo;
        }
        __syncthreads();

        #pragma unroll
        for (int kc2 = 0; kc2 < 2; kc2++) {
            const int kp0 = kc2 * 8;
            unsigned ah0 = Ah[rA * AP + kp0 + tg];
            unsigned ah1 = Ah[rB * AP + kp0 + tg];
            unsigned ah2 = Ah[rA * AP + kp0 + tg + 4];
            unsigned ah3 = Ah[rB * AP + kp0 + tg + 4];
            unsigned al0 = Al[rA * AP + kp0 + tg];
            unsigned al1 = Al[rB * AP + kp0 + tg];
            unsigned al2 = Al[rA * AP + kp0 + tg + 4];
            unsigned al3 = Al[rB * AP + kp0 + tg + 4];

            #pragma unroll
            for (int n = 0; n < 8; n++) {
                unsigned bh0 = Wth[(n * 8 + g) * WP + kp0 + tg];
                unsigned bh1 = Wth[(n * 8 + g) * WP + kp0 + tg + 4];
                unsigned bl0 = Wtl[(n * 8 + g) * WP + kp0 + tg];
                unsigned bl1 = Wtl[(n * 8 + g) * WP + kp0 + tg + 4];
                mma16(acc[n], ah0, ah1, ah2, ah3, bh0, bh1);
                mma16(acc[n], ah0, ah1, ah2, ah3, bl0, bl1);
                mma16(acc[n], al0, al1, al2, al3, bh0, bh1);
            }
        }
    }

    #pragma unroll
    for (int n = 0; n < 8; n++) {
        float2 o0, o1;
        o0.x = acc[n][0]; o0.y = acc[n][1];
        o1.x = acc[n][2]; o1.y = acc[n][3];
        *(float2*)&C[(size_t)(m0 + rA) * CDIM + n0 + n * 8 + 2 * tg] = o0;
        *(float2*)&C[(size_t)(m0 + rB) * CDIM + n0 + n * 8 + 2 * tg] = o1;
    }
}

extern "C" void kernel_launch(void* const* d_in, const int* in_sizes, int n_in,
                              void* d_out, int out_size)
{
    const float* X  = (const float*)d_in[0];
    const float* Wq = (const float*)d_in[1];
    const float* Wk = (const float*)d_in[2];
    const float* Wv = (const float*)d_in[3];
    const float* Wo = (const float*)d_in[4];
    float* out = (float*)d_out;

    cudaFuncSetAttribute(attn_kernel,
                         cudaFuncAttributeMaxDynamicSharedMemorySize, ATTN_SMEM);

    dim3 g1(SEQ / 128, 16, BATCH);
    qkv_mma<<<g1, 256, QKV_SMEM>>>(X, Wq, Wk, Wv);

    dim3 g2(SEQ / BM, NH, BATCH);
    attn_kernel<<<g2, 256, ATTN_SMEM>>>();

    dim3 g3(SEQ / 128, CDIM / 64, BATCH);
    out_mma<<<g3, 256, OUT_SMEM>>>(Wo, out);
}

// round 6
// speedup vs baseline: 8.9986x; 1.0704x over previous
#include <cuda_runtime.h>
#include <math.h>
#include <stdint.h>

#define SEQ   4096
#define CDIM  512
#define KDIM  256
#define VDIM  512
#define NH    8
#define DK    32
#define DV    64
#define BATCH 2

#define BM 128
#define BN 64

// Scratch (allocation-free per harness rules)
__device__ float g_q [BATCH * SEQ * KDIM];
__device__ float g_k [BATCH * SEQ * KDIM];
__device__ float g_v [BATCH * SEQ * VDIM];
__device__ float g_ao[BATCH * SEQ * VDIM];

// ---------------------------------------------------------------------------
// bf16 helpers
// ---------------------------------------------------------------------------
__device__ __forceinline__ void bsplit(float v0, float v1, unsigned& hi, unsigned& lo)
{
    asm("cvt.rn.bf16x2.f32 %0, %1, %2;" : "=r"(hi) : "f"(v1), "f"(v0));
    float h0 = __uint_as_float(hi << 16);
    float h1 = __uint_as_float(hi & 0xffff0000u);
    asm("cvt.rn.bf16x2.f32 %0, %1, %2;" : "=r"(lo) : "f"(v1 - h1), "f"(v0 - h0));
}

__device__ __forceinline__ void mma16(float c[4],
                                      unsigned a0, unsigned a1, unsigned a2, unsigned a3,
                                      unsigned b0, unsigned b1)
{
    asm volatile(
        "mma.sync.aligned.m16n8k16.row.col.f32.bf16.bf16.f32 "
        "{%0,%1,%2,%3},{%4,%5,%6,%7},{%8,%9},{%0,%1,%2,%3};"
        : "+f"(c[0]), "+f"(c[1]), "+f"(c[2]), "+f"(c[3])
        : "r"(a0), "r"(a1), "r"(a2), "r"(a3), "r"(b0), "r"(b1));
}

__device__ __forceinline__ unsigned sptr(const void* p) {
    return (unsigned)__cvta_generic_to_shared(p);
}

__device__ __forceinline__ void ldsm4(unsigned& r0, unsigned& r1,
                                      unsigned& r2, unsigned& r3, unsigned a)
{
    asm volatile("ldmatrix.sync.aligned.m8n8.x4.shared.b16 {%0,%1,%2,%3}, [%4];"
                 : "=r"(r0), "=r"(r1), "=r"(r2), "=r"(r3) : "r"(a));
}

// Lane offsets (in words) for ldmatrix address generation.
// A-fragment x4: matrices (m0-7,k0-7),(m8-15,k0-7),(m0-7,k8-15),(m8-15,k8-15)
#define AROW(l) (((l) & 7) + ((((l) >> 3) & 1) << 3))
#define ACOL(l) ((((l) >> 4) & 1) * 4)
// B-fragment x4 covering n-pair: (n,k0-7),(n,k8-15),(n+1,k0-7),(n+1,k8-15)
#define BROW(l) (((l) & 7) + ((((l) >> 4) & 1) << 3))
#define BCOL(l) ((((l) >> 3) & 1) * 4)

// ---------------------------------------------------------------------------
// Kernel 1: fused QKV projection, bf16 mma, 3-term split, ldmatrix loads.
// ---------------------------------------------------------------------------
#define AP 20
#define WP 20
#define QKV_SMEM ((2*128*AP + 2*64*WP) * 4)   // 30720 B

__global__ __launch_bounds__(256) void qkv_mma(
    const float* __restrict__ X,
    const float* __restrict__ Wq,
    const float* __restrict__ Wk,
    const float* __restrict__ Wv)
{
    extern __shared__ unsigned smg[];
    unsigned* Ah  = smg;
    unsigned* Al  = Ah  + 128 * AP;
    unsigned* Wth = Al  + 128 * AP;
    unsigned* Wtl = Wth + 64 * WP;

    const int b  = blockIdx.z;
    const int m0 = blockIdx.x * 128;
    const int by = blockIdx.y;

    const float* Wpt; int nbase, ldw, ldo; float* outp; float scale = 1.0f;
    if (by < 4) {
        Wpt = Wq; nbase = by * 64;       ldw = KDIM; ldo = KDIM;
        outp = g_q + (size_t)b * SEQ * KDIM;
        scale = 0.17677669529663687f;
    } else if (by < 8) {
        Wpt = Wk; nbase = (by - 4) * 64; ldw = KDIM; ldo = KDIM;
        outp = g_k + (size_t)b * SEQ * KDIM;
    } else {
        Wpt = Wv; nbase = (by - 8) * 64; ldw = VDIM; ldo = VDIM;
        outp = g_v + (size_t)b * SEQ * VDIM;
    }

    const float* A = X + (size_t)b * CDIM * SEQ;
    const int t    = threadIdx.x;
    const int w    = t >> 5;
    const int lane = t & 31;
    const int g    = lane >> 2;
    const int tg   = lane & 3;
    const int rA   = 16 * w + g;
    const int rB   = rA + 8;

    const unsigned aw = (unsigned)((16 * w + AROW(lane)) * AP + ACOL(lane)) * 4;
    const unsigned bw = (unsigned)(BROW(lane) * WP + BCOL(lane)) * 4;
    const unsigned aH = sptr(Ah) + aw,  aL = sptr(Al) + aw;
    const unsigned bH = sptr(Wth) + bw, bL = sptr(Wtl) + bw;

    float acc[8][4];
    #pragma unroll
    for (int n = 0; n < 8; n++)
        #pragma unroll
        for (int j = 0; j < 4; j++) acc[n][j] = 0.0f;

    for (int k0 = 0; k0 < CDIM; k0 += 32) {
        __syncthreads();
        #pragma unroll
        for (int i = t; i < 128 * 16; i += 256) {
            int m = i & 127, kp = i >> 7;
            float v0 = A[(size_t)(k0 + 2 * kp)     * SEQ + m0 + m];
            float v1 = A[(size_t)(k0 + 2 * kp + 1) * SEQ + m0 + m];
            unsigned hi, lo; bsplit(v0, v1, hi, lo);
            Ah[m * AP + kp] = hi; Al[m * AP + kp] = lo;
        }
        #pragma unroll
        for (int i = t; i < 64 * 16; i += 256) {
            int n = i & 63, kp = i >> 6;
            float v0 = Wpt[(size_t)(k0 + 2 * kp)     * ldw + nbase + n];
            float v1 = Wpt[(size_t)(k0 + 2 * kp + 1) * ldw + nbase + n];
            unsigned hi, lo; bsplit(v0, v1, hi, lo);
            Wth[n * WP + kp] = hi; Wtl[n * WP + kp] = lo;
        }
        __syncthreads();

        #pragma unroll
        for (int kc2 = 0; kc2 < 2; kc2++) {
            const unsigned ko = kc2 * 8 * 4;
            unsigned ah0, ah1, ah2, ah3, al0, al1, al2, al3;
            ldsm4(ah0, ah1, ah2, ah3, aH + ko);
            ldsm4(al0, al1, al2, al3, aL + ko);

            #pragma unroll
            for (int n2 = 0; n2 < 4; n2++) {
                const unsigned no = (unsigned)(n2 * 16 * WP) * 4 + ko;
                unsigned h0, h1, h2, h3, q0, q1, q2, q3;
                ldsm4(h0, h1, h2, h3, bH + no);
                ldsm4(q0, q1, q2, q3, bL + no);
                mma16(acc[2*n2],   ah0, ah1, ah2, ah3, h0, h1);
                mma16(acc[2*n2],   ah0, ah1, ah2, ah3, q0, q1);
                mma16(acc[2*n2],   al0, al1, al2, al3, h0, h1);
                mma16(acc[2*n2+1], ah0, ah1, ah2, ah3, h2, h3);
                mma16(acc[2*n2+1], ah0, ah1, ah2, ah3, q2, q3);
                mma16(acc[2*n2+1], al0, al1, al2, al3, h2, h3);
            }
        }
    }

    #pragma unroll
    for (int n = 0; n < 8; n++) {
        float2 o0, o1;
        o0.x = acc[n][0] * scale; o0.y = acc[n][1] * scale;
        o1.x = acc[n][2] * scale; o1.y = acc[n][3] * scale;
        *(float2*)&outp[(size_t)(m0 + rA) * ldo + nbase + n * 8 + 2 * tg] = o0;
        *(float2*)&outp[(size_t)(m0 + rB) * ldo + nbase + n * 8 + 2 * tg] = o1;
    }
}

// ---------------------------------------------------------------------------
// Kernel 2: causal flash attention, bf16 mma + ldmatrix.
// ---------------------------------------------------------------------------
#define QP 20
#define KP 20
#define VTP 36
#define PP 36

#define SM_QH 0
#define SM_QL (SM_QH + 128 * QP)
#define SM_KH (SM_QL + 128 * QP)
#define SM_KL (SM_KH + 64 * KP)
#define SM_VH (SM_KL + 64 * KP)
#define SM_VL (SM_VH + 64 * VTP)
#define SM_PH (SM_VL + 64 * VTP)
#define SM_PL (SM_PH + 128 * PP)
#define ATTN_SMEM ((SM_PL + 128 * PP) * 4)   // 86016 B

__global__ __launch_bounds__(256, 2) void attn_kernel()
{
    extern __shared__ unsigned sma[];
    unsigned* Qh  = sma + SM_QH;
    unsigned* Ql  = sma + SM_QL;
    unsigned* Kh  = sma + SM_KH;
    unsigned* Kl  = sma + SM_KL;
    unsigned* Vth = sma + SM_VH;
    unsigned* Vtl = sma + SM_VL;
    unsigned* Psh = sma + SM_PH;
    unsigned* Psl = sma + SM_PL;

    const int qb = gridDim.x - 1 - blockIdx.x;
    const int h  = blockIdx.y;
    const int b  = blockIdx.z;
    const int t  = threadIdx.x;
    const int w    = t >> 5;
    const int lane = t & 31;
    const int g    = lane >> 2;
    const int tg   = lane & 3;

    const int rA = 16 * w + g;
    const int rB = rA + 8;

    const float* Qp = g_q + ((size_t)b * SEQ + qb * BM) * KDIM + h * DK;
    const float* Kp = g_k + (size_t)b * SEQ * KDIM + h * DK;
    const float* Vp = g_v + (size_t)b * SEQ * VDIM + h * DV;

    // ldmatrix lane bases (byte addresses)
    const unsigned qw = (unsigned)((16 * w + AROW(lane)) * QP + ACOL(lane)) * 4;
    const unsigned pw = (unsigned)((16 * w + AROW(lane)) * PP + ACOL(lane)) * 4;
    const unsigned kw = (unsigned)(BROW(lane) * KP + BCOL(lane)) * 4;
    const unsigned vw = (unsigned)(BROW(lane) * VTP + BCOL(lane)) * 4;
    const unsigned aQH = sptr(Qh) + qw,  aQL = sptr(Ql) + qw;
    const unsigned aPH = sptr(Psh) + pw, aPL = sptr(Psl) + pw;
    const unsigned aKH = sptr(Kh) + kw,  aKL = sptr(Kl) + kw;
    const unsigned aVH = sptr(Vth) + vw, aVL = sptr(Vtl) + vw;

    // Q fill
    for (int i = t; i < BM * 16; i += 256) {
        int row = i >> 4, kp = i & 15;
        float2 v2 = *(const float2*)&Qp[(size_t)row * KDIM + 2 * kp];
        unsigned hi, lo; bsplit(v2.x, v2.y, hi, lo);
        Qh[row * QP + kp] = hi; Ql[row * QP + kp] = lo;
    }

    float m_i[2] = {-1e30f, -1e30f};
    float l_i[2] = {0.0f, 0.0f};
    float acc[8][4];
    #pragma unroll
    for (int n = 0; n < 8; n++)
        #pragma unroll
        for (int j = 0; j < 4; j++) acc[n][j] = 0.0f;

    const int kb_max = 2 * qb + 1;
    for (int kb = 0; kb <= kb_max; kb++) {
        __syncthreads();

        // K fill
        for (int i = t; i < BN * 16; i += 256) {
            int key = i >> 4, kp = i & 15;
            float2 v2 = *(const float2*)&Kp[(size_t)(kb * BN + key) * KDIM + 2 * kp];
            unsigned hi, lo; bsplit(v2.x, v2.y, hi, lo);
            Kh[key * KP + kp] = hi; Kl[key * KP + kp] = lo;
        }
        // V fill transposed (key-pairs)
        for (int i = t; i < 64 * 32; i += 256) {
            int vc = i & 63, pr = i >> 6;
            float v0 = Vp[(size_t)(kb * BN + 2 * pr)     * VDIM + vc];
            float v1 = Vp[(size_t)(kb * BN + 2 * pr + 1) * VDIM + vc];
            unsigned hi, lo; bsplit(v0, v1, hi, lo);
            Vth[vc * VTP + pr] = hi; Vtl[vc * VTP + pr] = lo;
        }
        __syncthreads();

        // ---- QK
        float s[8][4];
        #pragma unroll
        for (int n = 0; n < 8; n++)
            #pragma unroll
            for (int j = 0; j < 4; j++) s[n][j] = 0.0f;

        #pragma unroll
        for (int kc2 = 0; kc2 < 2; kc2++) {
            const unsigned ko = kc2 * 8 * 4;
            unsigned ah0, ah1, ah2, ah3, al0, al1, al2, al3;
            ldsm4(ah0, ah1, ah2, ah3, aQH + ko);
            ldsm4(al0, al1, al2, al3, aQL + ko);

            #pragma unroll
            for (int n2 = 0; n2 < 4; n2++) {
                const unsigned no = (unsigned)(n2 * 16 * KP) * 4 + ko;
                unsigned h0, h1, h2, h3, q0, q1, q2, q3;
                ldsm4(h0, h1, h2, h3, aKH + no);
                ldsm4(q0, q1, q2, q3, aKL + no);
                mma16(s[2*n2],   ah0, ah1, ah2, ah3, h0, h1);
                mma16(s[2*n2],   ah0, ah1, ah2, ah3, q0, q1);
                mma16(s[2*n2],   al0, al1, al2, al3, h0, h1);
                mma16(s[2*n2+1], ah0, ah1, ah2, ah3, h2, h3);
                mma16(s[2*n2+1], ah0, ah1, ah2, ah3, q2, q3);
                mma16(s[2*n2+1], al0, al1, al2, al3, h2, h3);
            }
        }

        // ---- causal mask
        if (kb >= 2 * qb) {
            const int rowA = qb * BM + rA;
            const int rowB = rowA + 8;
            #pragma unroll
            for (int n = 0; n < 8; n++) {
                int c = kb * BN + n * 8 + 2 * tg;
                if (c     > rowA) s[n][0] = -1e30f;
                if (c + 1 > rowA) s[n][1] = -1e30f;
                if (c     > rowB) s[n][2] = -1e30f;
                if (c + 1 > rowB) s[n][3] = -1e30f;
            }
        }

        // ---- online softmax; store P split bf16
        #pragma unroll
        for (int half = 0; half < 2; half++) {
            const int j0 = half * 2;
            float mloc = s[0][j0];
            #pragma unroll
            for (int n = 0; n < 8; n++) {
                mloc = fmaxf(mloc, s[n][j0]);
                mloc = fmaxf(mloc, s[n][j0 + 1]);
            }
            mloc = fmaxf(mloc, __shfl_xor_sync(0xffffffffu, mloc, 1));
            mloc = fmaxf(mloc, __shfl_xor_sync(0xffffffffu, mloc, 2));

            float mn   = fmaxf(m_i[half], mloc);
            float corr = __expf(m_i[half] - mn);
            m_i[half] = mn;

            const int prow = (half == 0 ? rA : rB);
            float ps = 0.0f;
            #pragma unroll
            for (int n = 0; n < 8; n++) {
                float p0 = __expf(s[n][j0]     - mn);
                float p1 = __expf(s[n][j0 + 1] - mn);
                ps += p0 + p1;
                unsigned hi, lo; bsplit(p0, p1, hi, lo);
                Psh[prow * PP + n * 4 + tg] = hi;
                Psl[prow * PP + n * 4 + tg] = lo;
            }
            ps += __shfl_xor_sync(0xffffffffu, ps, 1);
            ps += __shfl_xor_sync(0xffffffffu, ps, 2);

            l_i[half] = l_i[half] * corr + ps;
            #pragma unroll
            for (int n = 0; n < 8; n++) {
                acc[n][j0]     *= corr;
                acc[n][j0 + 1] *= corr;
            }
        }
        __syncwarp();

        // ---- PV
        #pragma unroll
        for (int kc2 = 0; kc2 < 4; kc2++) {
            const unsigned ko = kc2 * 8 * 4;
            unsigned ph0, ph1, ph2, ph3, pl0, pl1, pl2, pl3;
            ldsm4(ph0, ph1, ph2, ph3, aPH + ko);
            ldsm4(pl0, pl1, pl2, pl3, aPL + ko);

            #pragma unroll
            for (int n2 = 0; n2 < 4; n2++) {
                const unsigned no = (unsigned)(n2 * 16 * VTP) * 4 + ko;
                unsigned h0, h1, h2, h3, q0, q1, q2, q3;
                ldsm4(h0, h1, h2, h3, aVH + no);
                ldsm4(q0, q1, q2, q3, aVL + no);
                mma16(acc[2*n2],   ph0, ph1, ph2, ph3, h0, h1);
                mma16(acc[2*n2],   pl0, pl1, pl2, pl3, h0, h1);
                mma16(acc[2*n2],   ph0, ph1, ph2, ph3, q0, q1);
                mma16(acc[2*n2+1], ph0, ph1, ph2, ph3, h2, h3);
                mma16(acc[2*n2+1], pl0, pl1, pl2, pl3, h2, h3);
                mma16(acc[2*n2+1], ph0, ph1, ph2, ph3, q2, q3);
            }
        }
    }

    // ---- epilogue
    float inv0 = 1.0f / l_i[0];
    float inv1 = 1.0f / l_i[1];
    float* Op = g_ao + ((size_t)b * SEQ + qb * BM) * VDIM + h * DV;
    #pragma unroll
    for (int n = 0; n < 8; n++) {
        float2 o0; o0.x = acc[n][0] * inv0; o0.y = acc[n][1] * inv0;
        float2 o1; o1.x = acc[n][2] * inv1; o1.y = acc[n][3] * inv1;
        *(float2*)&Op[(size_t)rA * VDIM + n * 8 + 2 * tg] = o0;
        *(float2*)&Op[(size_t)rB * VDIM + n * 8 + 2 * tg] = o1;
    }
}

// ---------------------------------------------------------------------------
// Kernel 3: output projection bf16 mma + ldmatrix.
// ---------------------------------------------------------------------------
#define OUT_SMEM ((2*128*AP + 2*64*WP) * 4)

__global__ __launch_bounds__(256) void out_mma(
    const float* __restrict__ Wo, float* __restrict__ out)
{
    extern __shared__ unsigned smo[];
    unsigned* Ah  = smo;
    unsigned* Al  = Ah  + 128 * AP;
    unsigned* Wth = Al  + 128 * AP;
    unsigned* Wtl = Wth + 64 * WP;

    const int b  = blockIdx.z;
    const int m0 = blockIdx.x * 128;
    const int n0 = blockIdx.y * 64;

    const float* A = g_ao + (size_t)b * SEQ * VDIM;
    float* C = out + (size_t)b * SEQ * CDIM;

    const int t    = threadIdx.x;
    const int w    = t >> 5;
    const int lane = t & 31;
    const int g    = lane >> 2;
    const int tg   = lane & 3;
    const int rA   = 16 * w + g;
    const int rB   = rA + 8;

    const unsigned aw = (unsigned)((16 * w + AROW(lane)) * AP + ACOL(lane)) * 4;
    const unsigned bw = (unsigned)(BROW(lane) * WP + BCOL(lane)) * 4;
    const unsigned aH = sptr(Ah) + aw,  aL = sptr(Al) + aw;
    const unsigned bH = sptr(Wth) + bw, bL = sptr(Wtl) + bw;

    float acc[8][4];
    #pragma unroll
    for (int n = 0; n < 8; n++)
        #pragma unroll
        for (int j = 0; j < 4; j++) acc[n][j] = 0.0f;

    for (int k0 = 0; k0 < VDIM; k0 += 32) {
        __syncthreads();
        #pragma unroll
        for (int i = t; i < 128 * 16; i += 256) {
            int m = i >> 4, kp = i & 15;
            float2 v2 = *(const float2*)&A[(size_t)(m0 + m) * VDIM + k0 + 2 * kp];
            unsigned hi, lo; bsplit(v2.x, v2.y, hi, lo);
            Ah[m * AP + kp] = hi; Al[m * AP + kp] = lo;
        }
        #pragma unroll
        for (int i = t; i < 64 * 16; i += 256) {
            int n = i & 63, kp = i >> 6;
            float v0 = Wo[(size_t)(k0 + 2 * kp)     * CDIM + n0 + n];
            float v1 = Wo[(size_t)(k0 + 2 * kp + 1) * CDIM + n0 + n];
            unsigned hi, lo; bsplit(v0, v1, hi, lo);
            Wth[n * WP + kp] = hi; Wtl[n * WP + kp] = lo;
        }
        __syncthreads();

        #pragma unroll
        for (int kc2 = 0; kc2 < 2; kc2++) {
            const unsigned ko = kc2 * 8 * 4;
            unsigned ah0, ah1, ah2, ah3, al0, al1, al2, al3;
            ldsm4(ah0, ah1, ah2, ah3, aH + ko);
            ldsm4(al0, al1, al2, al3, aL + ko);

            #pragma unroll
            for (int n2 = 0; n2 < 4; n2++) {
                const unsigned no = (unsigned)(n2 * 16 * WP) * 4 + ko;
                unsigned h0, h1, h2, h3, q0, q1, q2, q3;
                ldsm4(h0, h1, h2, h3, bH + no);
                ldsm4(q0, q1, q2, q3, bL + no);
                mma16(acc[2*n2],   ah0, ah1, ah2, ah3, h0, h1);
                mma16(acc[2*n2],   ah0, ah1, ah2, ah3, q0, q1);
                mma16(acc[2*n2],   al0, al1, al2, al3, h0, h1);
                mma16(acc[2*n2+1], ah0, ah1, ah2, ah3, h2, h3);
                mma16(acc[2*n2+1], ah0, ah1, ah2, ah3, q2, q3);
                mma16(acc[2*n2+1], al0, al1, al2, al3, h2, h3);
            }
        }
    }

    #pragma unroll
    for (int n = 0; n < 8; n++) {
        float2 o0, o1;
        o0.x = acc[n][0]; o0.y = acc[n][1];
        o1.x = acc[n][2]; o1.y = acc[n][3];
        *(float2*)&C[(size_t)(m0 + rA) * CDIM + n0 + n * 8 + 2 * tg] = o0;
        *(float2*)&C[(size_t)(m0 + rB) * CDIM + n0 + n * 8 + 2 * tg] = o1;
    }
}

extern "C" void kernel_launch(void* const* d_in, const int* in_sizes, int n_in,
                              void* d_out, int out_size)
{
    const float* X  = (const float*)d_in[0];
    const float* Wq = (const float*)d_in[1];
    const float* Wk = (const float*)d_in[2];
    const float* Wv = (const float*)d_in[3];
    const float* Wo = (const float*)d_in[4];
    float* out = (float*)d_out;

    cudaFuncSetAttribute(attn_kernel,
                         cudaFuncAttributeMaxDynamicSharedMemorySize, ATTN_SMEM);

    dim3 g1(SEQ / 128, 16, BATCH);
    qkv_mma<<<g1, 256, QKV_SMEM>>>(X, Wq, Wk, Wv);

    dim3 g2(SEQ / BM, NH, BATCH);
    attn_kernel<<<g2, 256, ATTN_SMEM>>>();

    dim3 g3(SEQ / 128, CDIM / 64, BATCH);
    out_mma<<<g3, 256, OUT_SMEM>>>(Wo, out);
}

// round 7
// speedup vs baseline: 10.7792x; 1.1979x over previous
#include <cuda_runtime.h>
#include <math.h>
#include <stdint.h>

#define SEQ   4096
#define CDIM  512
#define KDIM  256
#define VDIM  512
#define NH    8
#define DK    32
#define DV    64
#define BATCH 2

#define BM 128
#define BN 64

// Scratch (allocation-free per harness rules)
__device__ unsigned g_qh[BATCH * SEQ * NH * 16];   // Q scaled, split hi, [b][s][h][kp]
__device__ unsigned g_ql[BATCH * SEQ * NH * 16];
__device__ unsigned g_kh[BATCH * SEQ * NH * 16];
__device__ unsigned g_kl[BATCH * SEQ * NH * 16];
__device__ unsigned g_vth[BATCH * NH * DV * (SEQ / 2)];  // V^T split, [b][h][vc][pair]
__device__ unsigned g_vtl[BATCH * NH * DV * (SEQ / 2)];
__device__ float    g_ao [BATCH * SEQ * VDIM];

// ---------------------------------------------------------------------------
// helpers
// ---------------------------------------------------------------------------
__device__ __forceinline__ void bsplit(float v0, float v1, unsigned& hi, unsigned& lo)
{
    asm("cvt.rn.bf16x2.f32 %0, %1, %2;" : "=r"(hi) : "f"(v1), "f"(v0));
    float h0 = __uint_as_float(hi << 16);
    float h1 = __uint_as_float(hi & 0xffff0000u);
    asm("cvt.rn.bf16x2.f32 %0, %1, %2;" : "=r"(lo) : "f"(v1 - h1), "f"(v0 - h0));
}

__device__ __forceinline__ void mma16(float c[4],
                                      unsigned a0, unsigned a1, unsigned a2, unsigned a3,
                                      unsigned b0, unsigned b1)
{
    asm volatile(
        "mma.sync.aligned.m16n8k16.row.col.f32.bf16.bf16.f32 "
        "{%0,%1,%2,%3},{%4,%5,%6,%7},{%8,%9},{%0,%1,%2,%3};"
        : "+f"(c[0]), "+f"(c[1]), "+f"(c[2]), "+f"(c[3])
        : "r"(a0), "r"(a1), "r"(a2), "r"(a3), "r"(b0), "r"(b1));
}

__device__ __forceinline__ unsigned sptr(const void* p) {
    return (unsigned)__cvta_generic_to_shared(p);
}

__device__ __forceinline__ void ldsm4(unsigned& r0, unsigned& r1,
                                      unsigned& r2, unsigned& r3, unsigned a)
{
    asm volatile("ldmatrix.sync.aligned.m8n8.x4.shared.b16 {%0,%1,%2,%3}, [%4];"
                 : "=r"(r0), "=r"(r1), "=r"(r2), "=r"(r3) : "r"(a));
}

__device__ __forceinline__ void cpa16(unsigned dst, const void* src) {
    asm volatile("cp.async.cg.shared.global [%0], [%1], 16;" :: "r"(dst), "l"(src));
}
#define CPA_COMMIT() asm volatile("cp.async.commit_group;")
#define CPA_WAIT(N)  asm volatile("cp.async.wait_group %0;" :: "n"(N))

// Lane offsets (in words) for ldmatrix address generation.
#define AROW(l) (((l) & 7) + ((((l) >> 3) & 1) << 3))
#define ACOL(l) ((((l) >> 4) & 1) * 4)
#define BROW(l) (((l) & 7) + ((((l) >> 4) & 1) << 3))
#define BCOL(l) ((((l) >> 3) & 1) * 4)

// ---------------------------------------------------------------------------
// Kernel 1: fused QKV projection, bf16 mma + ldmatrix; epilogue writes
// pre-split bf16x2 hi/lo forms for Q (scaled), K and V^T (via shfl pairing).
// ---------------------------------------------------------------------------
#define AP 20
#define WP 20
#define QKV_SMEM ((2*128*AP + 2*64*WP) * 4)   // 30720 B

__global__ __launch_bounds__(256) void qkv_mma(
    const float* __restrict__ X,
    const float* __restrict__ Wq,
    const float* __restrict__ Wk,
    const float* __restrict__ Wv)
{
    extern __shared__ unsigned smg[];
    unsigned* Ah  = smg;
    unsigned* Al  = Ah  + 128 * AP;
    unsigned* Wth = Al  + 128 * AP;
    unsigned* Wtl = Wth + 64 * WP;

    const int b  = blockIdx.z;
    const int m0 = blockIdx.x * 128;
    const int by = blockIdx.y;

    const float* Wpt; int nbase, ldw;
    if (by < 4)      { Wpt = Wq; nbase = by * 64;       ldw = KDIM; }
    else if (by < 8) { Wpt = Wk; nbase = (by - 4) * 64; ldw = KDIM; }
    else             { Wpt = Wv; nbase = (by - 8) * 64; ldw = VDIM; }

    const float* A = X + (size_t)b * CDIM * SEQ;
    const int t    = threadIdx.x;
    const int w    = t >> 5;
    const int lane = t & 31;
    const int g    = lane >> 2;
    const int tg   = lane & 3;
    const int rA   = 16 * w + g;
    const int rB   = rA + 8;

    const unsigned aw = (unsigned)((16 * w + AROW(lane)) * AP + ACOL(lane)) * 4;
    const unsigned bw = (unsigned)(BROW(lane) * WP + BCOL(lane)) * 4;
    const unsigned aH = sptr(Ah) + aw,  aL = sptr(Al) + aw;
    const unsigned bH = sptr(Wth) + bw, bL = sptr(Wtl) + bw;

    float acc[8][4];
    #pragma unroll
    for (int n = 0; n < 8; n++)
        #pragma unroll
        for (int j = 0; j < 4; j++) acc[n][j] = 0.0f;

    for (int k0 = 0; k0 < CDIM; k0 += 32) {
        __syncthreads();
        #pragma unroll
        for (int i = t; i < 128 * 16; i += 256) {
            int m = i & 127, kp = i >> 7;
            float v0 = A[(size_t)(k0 + 2 * kp)     * SEQ + m0 + m];
            float v1 = A[(size_t)(k0 + 2 * kp + 1) * SEQ + m0 + m];
            unsigned hi, lo; bsplit(v0, v1, hi, lo);
            Ah[m * AP + kp] = hi; Al[m * AP + kp] = lo;
        }
        #pragma unroll
        for (int i = t; i < 64 * 16; i += 256) {
            int n = i & 63, kp = i >> 6;
            float v0 = Wpt[(size_t)(k0 + 2 * kp)     * ldw + nbase + n];
            float v1 = Wpt[(size_t)(k0 + 2 * kp + 1) * ldw + nbase + n];
            unsigned hi, lo; bsplit(v0, v1, hi, lo);
            Wth[n * WP + kp] = hi; Wtl[n * WP + kp] = lo;
        }
        __syncthreads();

        #pragma unroll
        for (int kc2 = 0; kc2 < 2; kc2++) {
            const unsigned ko = kc2 * 8 * 4;
            unsigned ah0, ah1, ah2, ah3, al0, al1, al2, al3;
            ldsm4(ah0, ah1, ah2, ah3, aH + ko);
            ldsm4(al0, al1, al2, al3, aL + ko);

            #pragma unroll
            for (int n2 = 0; n2 < 4; n2++) {
                const unsigned no = (unsigned)(n2 * 16 * WP) * 4 + ko;
                unsigned h0, h1, h2, h3, q0, q1, q2, q3;
                ldsm4(h0, h1, h2, h3, bH + no);
                ldsm4(q0, q1, q2, q3, bL + no);
                mma16(acc[2*n2],   ah0, ah1, ah2, ah3, h0, h1);
                mma16(acc[2*n2],   ah0, ah1, ah2, ah3, q0, q1);
                mma16(acc[2*n2],   al0, al1, al2, al3, h0, h1);
                mma16(acc[2*n2+1], ah0, ah1, ah2, ah3, h2, h3);
                mma16(acc[2*n2+1], ah0, ah1, ah2, ah3, q2, q3);
                mma16(acc[2*n2+1], al0, al1, al2, al3, h2, h3);
            }
        }
    }

    // ---- epilogue: write pre-split forms ----
    if (by < 8) {
        // Q (scaled) or K: pairs along d
        const float scale = (by < 4) ? 0.17677669529663687f : 1.0f;
        unsigned* dsth = (by < 4) ? g_qh : g_kh;
        unsigned* dstl = (by < 4) ? g_ql : g_kl;
        #pragma unroll
        for (int n = 0; n < 8; n++) {
            int col = nbase + n * 8 + 2 * tg;
            int h   = col >> 5;
            int kp  = (col & 31) >> 1;
            unsigned hi, lo;
            bsplit(acc[n][0] * scale, acc[n][1] * scale, hi, lo);
            size_t iA = ((size_t)(b * SEQ + m0 + rA) * NH + h) * 16 + kp;
            dsth[iA] = hi; dstl[iA] = lo;
            bsplit(acc[n][2] * scale, acc[n][3] * scale, hi, lo);
            size_t iB = ((size_t)(b * SEQ + m0 + rB) * NH + h) * 16 + kp;
            dsth[iB] = hi; dstl[iB] = lo;
        }
    } else {
        // V: transposed, pairs along rows (keys). Partner lane = lane^4 (g^1).
        const int h = by - 8;
        const int geven = (g & 1) == 0;
        const int prA = (m0 >> 1) + 8 * w + (g >> 1);   // key-pair index, rows rA-set
        const int prB = prA + 4;
        #pragma unroll
        for (int n = 0; n < 8; n++) {
            float o00 = acc[n][0], o01 = acc[n][1];
            float o10 = acc[n][2], o11 = acc[n][3];
            float q00 = __shfl_xor_sync(0xffffffffu, o00, 4);
            float q01 = __shfl_xor_sync(0xffffffffu, o01, 4);
            float q10 = __shfl_xor_sync(0xffffffffu, o10, 4);
            float q11 = __shfl_xor_sync(0xffffffffu, o11, 4);
            int   col = n * 8 + 2 * tg + (geven ? 0 : 1);
            float vA0 = geven ? o00 : q01;
            float vA1 = geven ? q00 : o01;
            float vB0 = geven ? o10 : q11;
            float vB1 = geven ? q10 : o11;
            size_t base = ((size_t)(b * NH + h) * DV + col) * (SEQ / 2);
            unsigned hi, lo;
            bsplit(vA0, vA1, hi, lo);
            g_vth[base + prA] = hi; g_vtl[base + prA] = lo;
            bsplit(vB0, vB1, hi, lo);
            g_vth[base + prB] = hi; g_vtl[base + prB] = lo;
        }
    }
}

// ---------------------------------------------------------------------------
// Kernel 2: causal flash attention.
// cp.async double-buffered K/V; Q via cp.async; P register-resident.
// ---------------------------------------------------------------------------
#define QP 20
#define KP 20
#define VTP 36

#define SM_QH  0
#define SM_QL  (SM_QH + 128 * QP)          // 2560
#define SM_K0  (SM_QL + 128 * QP)          // 5120 : K bufs, each 2*1280 (hi,lo)
#define SM_V0  (SM_K0 + 2 * 2 * 64 * KP)   // 10240 : V bufs, each 2*2304
#define ATTN_SMEM ((SM_V0 + 2 * 2 * 64 * VTP) * 4)   // 77824 B

__global__ __launch_bounds__(256, 2) void attn_kernel()
{
    extern __shared__ unsigned sma[];
    unsigned* Qh = sma + SM_QH;
    unsigned* Ql = sma + SM_QL;

    const int qb = gridDim.x - 1 - blockIdx.x;
    const int h  = blockIdx.y;
    const int b  = blockIdx.z;
    const int t  = threadIdx.x;
    const int w    = t >> 5;
    const int lane = t & 31;
    const int g    = lane >> 2;
    const int tg   = lane & 3;

    const int rA = 16 * w + g;
    const int rB = rA + 8;

    const unsigned* Kh_g = g_kh + ((size_t)b * SEQ * NH + h) * 16;
    const unsigned* Kl_g = g_kl + ((size_t)b * SEQ * NH + h) * 16;
    const unsigned* Vh_g = g_vth + (size_t)(b * NH + h) * DV * (SEQ / 2);
    const unsigned* Vl_g = g_vtl + (size_t)(b * NH + h) * DV * (SEQ / 2);

    // ldmatrix lane bases
    const unsigned qw = (unsigned)((16 * w + AROW(lane)) * QP + ACOL(lane)) * 4;
    const unsigned kw = (unsigned)(BROW(lane) * KP + BCOL(lane)) * 4;
    const unsigned vw = (unsigned)(BROW(lane) * VTP + BCOL(lane)) * 4;
    const unsigned aQH = sptr(Qh) + qw, aQL = sptr(Ql) + qw;
    const unsigned kbuf0 = sptr(sma + SM_K0);
    const unsigned vbuf0 = sptr(sma + SM_V0);

    // ---- prologue fills: Q + tile 0 (group 0)
    {
        const unsigned* Qh_g = g_qh + ((size_t)(b * SEQ + qb * BM) * NH + h) * 16;
        const unsigned* Ql_g = g_ql + ((size_t)(b * SEQ + qb * BM) * NH + h) * 16;
        #pragma unroll
        for (int i = t; i < 128 * 4; i += 256) {
            int row = i >> 2, seg = (i & 3) * 4;
            cpa16(sptr(Qh + row * QP + seg), Qh_g + (size_t)row * NH * 16 + seg);
            cpa16(sptr(Ql + row * QP + seg), Ql_g + (size_t)row * NH * 16 + seg);
        }
    }
    // K/V fill lambdas (macro-style)
    #define FILL_K(kb_, buf_)                                                   \
        { unsigned kb_base = kbuf0 + (unsigned)(buf_) * 2 * 64 * KP * 4;        \
          int i = t; { int row = i >> 2, seg = (i & 3) * 4;                     \
            size_t src = (size_t)((kb_) * BN + row) * NH * 16 + seg;            \
            cpa16(kb_base + (unsigned)(row * KP + seg) * 4, Kh_g + src);        \
            cpa16(kb_base + (unsigned)(64 * KP + row * KP + seg) * 4, Kl_g + src); } }
    #define FILL_V(kb_, buf_)                                                   \
        { unsigned vb_base = vbuf0 + (unsigned)(buf_) * 2 * 64 * VTP * 4;       \
          _Pragma("unroll")                                                     \
          for (int i = t; i < 64 * 8; i += 256) {                               \
            int vc = i >> 3, seg = (i & 7) * 4;                                 \
            size_t src = (size_t)vc * (SEQ / 2) + (kb_) * 32 + seg;             \
            cpa16(vb_base + (unsigned)(vc * VTP + seg) * 4, Vh_g + src);        \
            cpa16(vb_base + (unsigned)(64 * VTP + vc * VTP + seg) * 4, Vl_g + src); } }

    FILL_K(0, 0);
    FILL_V(0, 0);
    CPA_COMMIT();

    float m_i[2] = {-1e30f, -1e30f};
    float l_i[2] = {0.0f, 0.0f};
    float acc[8][4];
    #pragma unroll
    for (int n = 0; n < 8; n++)
        #pragma unroll
        for (int j = 0; j < 4; j++) acc[n][j] = 0.0f;

    const int kb_max = 2 * qb + 1;
    for (int kb = 0; kb <= kb_max; kb++) {
        const int buf = kb & 1;
        if (kb < kb_max) {
            FILL_K(kb + 1, buf ^ 1);
            FILL_V(kb + 1, buf ^ 1);
            CPA_COMMIT();
            CPA_WAIT(1);
        } else {
            CPA_WAIT(0);
        }
        __syncthreads();

        const unsigned aKH = kbuf0 + (unsigned)buf * 2 * 64 * KP * 4 + kw;
        const unsigned aKL = aKH + (unsigned)(64 * KP) * 4;
        const unsigned aVH = vbuf0 + (unsigned)buf * 2 * 64 * VTP * 4 + vw;
        const unsigned aVL = aVH + (unsigned)(64 * VTP) * 4;

        // ---- QK
        float s[8][4];
        #pragma unroll
        for (int n = 0; n < 8; n++)
            #pragma unroll
            for (int j = 0; j < 4; j++) s[n][j] = 0.0f;

        #pragma unroll
        for (int kc2 = 0; kc2 < 2; kc2++) {
            const unsigned ko = kc2 * 8 * 4;
            unsigned ah0, ah1, ah2, ah3, al0, al1, al2, al3;
            ldsm4(ah0, ah1, ah2, ah3, aQH + ko);
            ldsm4(al0, al1, al2, al3, aQL + ko);

            #pragma unroll
            for (int n2 = 0; n2 < 4; n2++) {
                const unsigned no = (unsigned)(n2 * 16 * KP) * 4 + ko;
                unsigned h0, h1, h2, h3, q0, q1, q2, q3;
                ldsm4(h0, h1, h2, h3, aKH + no);
                ldsm4(q0, q1, q2, q3, aKL + no);
                mma16(s[2*n2],   ah0, ah1, ah2, ah3, h0, h1);
                mma16(s[2*n2],   ah0, ah1, ah2, ah3, q0, q1);
                mma16(s[2*n2],   al0, al1, al2, al3, h0, h1);
                mma16(s[2*n2+1], ah0, ah1, ah2, ah3, h2, h3);
                mma16(s[2*n2+1], ah0, ah1, ah2, ah3, q2, q3);
                mma16(s[2*n2+1], al0, al1, al2, al3, h2, h3);
            }
        }

        // ---- causal mask
        if (kb >= 2 * qb) {
            const int rowA = qb * BM + rA;
            const int rowB = rowA + 8;
            #pragma unroll
            for (int n = 0; n < 8; n++) {
                int c = kb * BN + n * 8 + 2 * tg;
                if (c     > rowA) s[n][0] = -1e30f;
                if (c + 1 > rowA) s[n][1] = -1e30f;
                if (c     > rowB) s[n][2] = -1e30f;
                if (c + 1 > rowB) s[n][3] = -1e30f;
            }
        }

        // ---- online softmax; P assembled directly into A-fragment registers
        unsigned pH[4][4], pL[4][4];
        #pragma unroll
        for (int half = 0; half < 2; half++) {
            const int j0 = half * 2;
            float mloc = s[0][j0];
            #pragma unroll
            for (int n = 0; n < 8; n++) {
                mloc = fmaxf(mloc, s[n][j0]);
                mloc = fmaxf(mloc, s[n][j0 + 1]);
            }
            mloc = fmaxf(mloc, __shfl_xor_sync(0xffffffffu, mloc, 1));
            mloc = fmaxf(mloc, __shfl_xor_sync(0xffffffffu, mloc, 2));

            float mn   = fmaxf(m_i[half], mloc);
            float corr = __expf(m_i[half] - mn);
            m_i[half] = mn;

            float ps = 0.0f;
            #pragma unroll
            for (int n = 0; n < 8; n++) {
                float p0 = __expf(s[n][j0]     - mn);
                float p1 = __expf(s[n][j0 + 1] - mn);
                ps += p0 + p1;
                unsigned hi, lo; bsplit(p0, p1, hi, lo);
                const int slot = (n & 1) * 2 + half;   // a0/a1/a2/a3
                pH[n >> 1][slot] = hi;
                pL[n >> 1][slot] = lo;
            }
            ps += __shfl_xor_sync(0xffffffffu, ps, 1);
            ps += __shfl_xor_sync(0xffffffffu, ps, 2);

            l_i[half] = l_i[half] * corr + ps;
            #pragma unroll
            for (int n = 0; n < 8; n++) {
                acc[n][j0]     *= corr;
                acc[n][j0 + 1] *= corr;
            }
        }

        // ---- PV: acc += (P_hi + P_lo) @ V_hi + P_hi @ V_lo
        #pragma unroll
        for (int kc = 0; kc < 4; kc++) {
            const unsigned ko = kc * 8 * 4;
            #pragma unroll
            for (int n2 = 0; n2 < 4; n2++) {
                const unsigned no = (unsigned)(n2 * 16 * VTP) * 4 + ko;
                unsigned h0, h1, h2, h3, q0, q1, q2, q3;
                ldsm4(h0, h1, h2, h3, aVH + no);
                ldsm4(q0, q1, q2, q3, aVL + no);
                mma16(acc[2*n2],   pH[kc][0], pH[kc][1], pH[kc][2], pH[kc][3], h0, h1);
                mma16(acc[2*n2],   pL[kc][0], pL[kc][1], pL[kc][2], pL[kc][3], h0, h1);
                mma16(acc[2*n2],   pH[kc][0], pH[kc][1], pH[kc][2], pH[kc][3], q0, q1);
                mma16(acc[2*n2+1], pH[kc][0], pH[kc][1], pH[kc][2], pH[kc][3], h2, h3);
                mma16(acc[2*n2+1], pL[kc][0], pL[kc][1], pL[kc][2], pL[kc][3], h2, h3);
                mma16(acc[2*n2+1], pH[kc][0], pH[kc][1], pH[kc][2], pH[kc][3], q2, q3);
            }
        }
        __syncthreads();   // tile consumed; next iter may overwrite this buffer
    }

    // ---- epilogue
    float inv0 = 1.0f / l_i[0];
    float inv1 = 1.0f / l_i[1];
    float* Op = g_ao + ((size_t)b * SEQ + qb * BM) * VDIM + h * DV;
    #pragma unroll
    for (int n = 0; n < 8; n++) {
        float2 o0; o0.x = acc[n][0] * inv0; o0.y = acc[n][1] * inv0;
        float2 o1; o1.x = acc[n][2] * inv1; o1.y = acc[n][3] * inv1;
        *(float2*)&Op[(size_t)rA * VDIM + n * 8 + 2 * tg] = o0;
        *(float2*)&Op[(size_t)rB * VDIM + n * 8 + 2 * tg] = o1;
    }
}

// ---------------------------------------------------------------------------
// Kernel 3: output projection bf16 mma + ldmatrix (unchanged).
// ---------------------------------------------------------------------------
#define OUT_SMEM ((2*128*AP + 2*64*WP) * 4)

__global__ __launch_bounds__(256) void out_mma(
    const float* __restrict__ Wo, float* __restrict__ out)
{
    extern __shared__ unsigned smo[];
    unsigned* Ah  = smo;
    unsigned* Al  = Ah  + 128 * AP;
    unsigned* Wth = Al  + 128 * AP;
    unsigned* Wtl = Wth + 64 * WP;

    const int b  = blockIdx.z;
    const int m0 = blockIdx.x * 128;
    const int n0 = blockIdx.y * 64;

    const float* A = g_ao + (size_t)b * SEQ * VDIM;
    float* C = out + (size_t)b * SEQ * CDIM;

    const int t    = threadIdx.x;
    const int w    = t >> 5;
    const int lane = t & 31;
    const int g    = lane >> 2;
    const int tg   = lane & 3;
    const int rA   = 16 * w + g;
    const int rB   = rA + 8;

    const unsigned aw = (unsigned)((16 * w + AROW(lane)) * AP + ACOL(lane)) * 4;
    const unsigned bw = (unsigned)(BROW(lane) * WP + BCOL(lane)) * 4;
    const unsigned aH = sptr(Ah) + aw,  aL = sptr(Al) + aw;
    const unsigned bH = sptr(Wth) + bw, bL = sptr(Wtl) + bw;

    float acc[8][4];
    #pragma unroll
    for (int n = 0; n < 8; n++)
        #pragma unroll
        for (int j = 0; j < 4; j++) acc[n][j] = 0.0f;

    for (int k0 = 0; k0 < VDIM; k0 += 32) {
        __syncthreads();
        #pragma unroll
        for (int i = t; i < 128 * 16; i += 256) {
            int m = i >> 4, kp = i & 15;
            float2 v2 = *(const float2*)&A[(size_t)(m0 + m) * VDIM + k0 + 2 * kp];
            unsigned hi, lo; bsplit(v2.x, v2.y, hi, lo);
            Ah[m * AP + kp] = hi; Al[m * AP + kp] = lo;
        }
        #pragma unroll
        for (int i = t; i < 64 * 16; i += 256) {
            int n = i & 63, kp = i >> 6;
            float v0 = Wo[(size_t)(k0 + 2 * kp)     * CDIM + n0 + n];
            float v1 = Wo[(size_t)(k0 + 2 * kp + 1) * CDIM + n0 + n];
            unsigned hi, lo; bsplit(v0, v1, hi, lo);
            Wth[n * WP + kp] = hi; Wtl[n * WP + kp] = lo;
        }
        __syncthreads();

        #pragma unroll
        for (int kc2 = 0; kc2 < 2; kc2++) {
            const unsigned ko = kc2 * 8 * 4;
            unsigned ah0, ah1, ah2, ah3, al0, al1, al2, al3;
            ldsm4(ah0, ah1, ah2, ah3, aH + ko);
            ldsm4(al0, al1, al2, al3, aL + ko);

            #pragma unroll
            for (int n2 = 0; n2 < 4; n2++) {
                const unsigned no = (unsigned)(n2 * 16 * WP) * 4 + ko;
                unsigned h0, h1, h2, h3, q0, q1, q2, q3;
                ldsm4(h0, h1, h2, h3, bH + no);
                ldsm4(q0, q1, q2, q3, bL + no);
                mma16(acc[2*n2],   ah0, ah1, ah2, ah3, h0, h1);
                mma16(acc[2*n2],   ah0, ah1, ah2, ah3, q0, q1);
                mma16(acc[2*n2],   al0, al1, al2, al3, h0, h1);
                mma16(acc[2*n2+1], ah0, ah1, ah2, ah3, h2, h3);
                mma16(acc[2*n2+1], ah0, ah1, ah2, ah3, q2, q3);
                mma16(acc[2*n2+1], al0, al1, al2, al3, h2, h3);
            }
        }
    }

    #pragma unroll
    for (int n = 0; n < 8; n++) {
        float2 o0, o1;
        o0.x = acc[n][0]; o0.y = acc[n][1];
        o1.x = acc[n][2]; o1.y = acc[n][3];
        *(float2*)&C[(size_t)(m0 + rA) * CDIM + n0 + n * 8 + 2 * tg] = o0;
        *(float2*)&C[(size_t)(m0 + rB) * CDIM + n0 + n * 8 + 2 * tg] = o1;
    }
}

extern "C" void kernel_launch(void* const* d_in, const int* in_sizes, int n_in,
                              void* d_out, int out_size)
{
    const float* X  = (const float*)d_in[0];
    const float* Wq = (const float*)d_in[1];
    const float* Wk = (const float*)d_in[2];
    const float* Wv = (const float*)d_in[3];
    const float* Wo = (const float*)d_in[4];
    float* out = (float*)d_out;

    cudaFuncSetAttribute(attn_kernel,
                         cudaFuncAttributeMaxDynamicSharedMemorySize, ATTN_SMEM);

    dim3 g1(SEQ / 128, 16, BATCH);
    qkv_mma<<<g1, 256, QKV_SMEM>>>(X, Wq, Wk, Wv);

    dim3 g2(SEQ / BM, NH, BATCH);
    attn_kernel<<<g2, 256, ATTN_SMEM>>>();

    dim3 g3(SEQ / 128, CDIM / 64, BATCH);
    out_mma<<<g3, 256, OUT_SMEM>>>(Wo, out);
}